// round 3
// baseline (speedup 1.0000x reference)
#include <cuda_runtime.h>
#include <math.h>

// Problem constants
#define Bb   4
#define Nn   512
#define Dd   512
#define Hh   8
#define DHd  64
#define Kb   10
#define Mf   2048
#define Ll   4
#define TOK  (Bb*Nn)      // 2048
#define EPSf 1e-5f

// ---------------- scratch (device globals: no allocations allowed) ----------
__device__ float g_x[TOK*Dd];
__device__ float g_h[TOK*Dd];
__device__ float g_q[TOK*Dd];
__device__ float g_k[TOK*Dd];
__device__ float g_v[TOK*Dd];
__device__ float g_o[TOK*Dd];
__device__ float g_f[TOK*Mf];
__device__ float g_qrel[TOK*Hh*Kb];
__device__ int   g_idx[Bb*Nn*Nn];

// ---------------- distance bins (once per launch) ---------------------------
__global__ void idx_kernel(const float* __restrict__ coord) {
    int n = blockIdx.x, b = blockIdx.y, m = threadIdx.x;
    float2 cn = ((const float2*)coord)[b*Nn + n];
    float2 cm = ((const float2*)coord)[b*Nn + m];
    float dx = cn.x - cm.x, dy = cn.y - cm.y;
    float dist = sqrtf(dx*dx + dy*dy);
    int j = (int)floorf(dist);
    j = j < 0 ? 0 : (j > Kb-1 ? Kb-1 : j);
    g_idx[((size_t)(b*Nn + n))*Nn + m] = j;
}

// ---------------- layernorm: one block (256 thr) per row of 512 -------------
__global__ void ln_kernel(const float* __restrict__ x,
                          const float* __restrict__ g,
                          const float* __restrict__ b,
                          float* __restrict__ out) {
    int row = blockIdx.x;
    int tid = threadIdx.x;   // 256
    const float* xr = x + (size_t)row * Dd;
    float v0 = xr[tid], v1 = xr[tid + 256];

    __shared__ float red[8];
    float s = v0 + v1;
    #pragma unroll
    for (int o = 16; o > 0; o >>= 1) s += __shfl_xor_sync(0xffffffffu, s, o);
    if ((tid & 31) == 0) red[tid >> 5] = s;
    __syncthreads();
    float tot = 0.f;
    #pragma unroll
    for (int i = 0; i < 8; i++) tot += red[i];
    float mean = tot * (1.0f / Dd);
    __syncthreads();
    float d0 = v0 - mean, d1 = v1 - mean;
    float vs = d0*d0 + d1*d1;
    #pragma unroll
    for (int o = 16; o > 0; o >>= 1) vs += __shfl_xor_sync(0xffffffffu, vs, o);
    if ((tid & 31) == 0) red[tid >> 5] = vs;
    __syncthreads();
    float vtot = 0.f;
    #pragma unroll
    for (int i = 0; i < 8; i++) vtot += red[i];
    float inv = rsqrtf(vtot * (1.0f / Dd) + EPSf);

    out[(size_t)row*Dd + tid]       = d0 * inv * g[tid]       + b[tid];
    out[(size_t)row*Dd + tid + 256] = d1 * inv * g[tid + 256] + b[tid + 256];
}

// ---------------- qrel[tok,h,j] = q[tok, h*64:...] . rel_k[j] ---------------
__global__ void qrel_kernel(const float* __restrict__ relk) {
    int t = blockIdx.x * blockDim.x + threadIdx.x;
    if (t >= TOK*Hh*Kb) return;
    int j   = t % Kb;
    int h   = (t / Kb) % Hh;
    int tok = t / (Kb * Hh);
    const float* qrow = g_q + (size_t)tok*Dd + h*DHd;
    const float* rk   = relk + j*DHd;
    float dot = 0.f;
    #pragma unroll
    for (int d = 0; d < DHd; d++) dot += qrow[d] * rk[d];
    g_qrel[t] = dot;
}

// ---------------- fused attention: 4 query rows per block -------------------
// block: 128 threads. grid: (N/4, H, B).
__global__ void attn_kernel(const float* __restrict__ relv) {
    const int n0 = blockIdx.x * 4;
    const int h  = blockIdx.y;
    const int b  = blockIdx.z;
    const int tid = threadIdx.x;   // 128

    __shared__ __align__(16) float ks[128][65];   // K/V tile (reused)
    __shared__ float sc[4][512];                  // scores -> probs
    __shared__ float qs[4][64];
    __shared__ float qrs[4][Kb];
    __shared__ float pbin[4][Kb];
    __shared__ float part[2][4][64];
    __shared__ float red[16];

    // FIX: 4*64 = 256 elements loaded by 128 threads — must loop, not guard.
    for (int i = tid; i < 4*64; i += 128) {
        int qi = i >> 6, d = i & 63;
        qs[qi][d] = g_q[((size_t)(b*Nn + n0 + qi))*Dd + h*DHd + d];
    }
    if (tid < 4*Kb) {
        int qi = tid / Kb, j = tid % Kb;
        qrs[qi][j]  = g_qrel[(((size_t)(b*Nn + n0 + qi))*Hh + h)*Kb + j];
        pbin[qi][j] = 0.f;
    }
    __syncthreads();

    int myidx[4][4];
    // ---- phase 1: scores ----
    for (int mc = 0; mc < 4; mc++) {
        const float* kbase = g_k + ((size_t)(b*Nn + mc*128))*Dd + h*DHd;
        for (int i = tid; i < 128*64; i += 128) {
            int r = i >> 6, c = i & 63;
            ks[r][c] = kbase[(size_t)r*Dd + c];
        }
        __syncthreads();
        int m = mc*128 + tid;
        float dot[4] = {0.f, 0.f, 0.f, 0.f};
        #pragma unroll
        for (int d = 0; d < 64; d++) {
            float kv = ks[tid][d];
            #pragma unroll
            for (int qi = 0; qi < 4; qi++) dot[qi] += qs[qi][d] * kv;
        }
        #pragma unroll
        for (int qi = 0; qi < 4; qi++) {
            int ji = g_idx[((size_t)(b*Nn + n0 + qi))*Nn + m];
            myidx[qi][mc] = ji;
            sc[qi][m] = (dot[qi] + qrs[qi][ji]) * 0.125f;   // 1/sqrt(64)
        }
        __syncthreads();
    }

    // ---- phase 2: softmax + bin mass ----
    float gmax[4];
    {
        float lm[4];
        #pragma unroll
        for (int qi = 0; qi < 4; qi++) {
            float v = -1e30f;
            #pragma unroll
            for (int mc = 0; mc < 4; mc++) v = fmaxf(v, sc[qi][mc*128 + tid]);
            lm[qi] = v;
        }
        #pragma unroll
        for (int o = 16; o > 0; o >>= 1)
            #pragma unroll
            for (int qi = 0; qi < 4; qi++)
                lm[qi] = fmaxf(lm[qi], __shfl_xor_sync(0xffffffffu, lm[qi], o));
        if ((tid & 31) == 0) {
            int w = tid >> 5;
            #pragma unroll
            for (int qi = 0; qi < 4; qi++) red[qi*4 + w] = lm[qi];
        }
        __syncthreads();
        #pragma unroll
        for (int qi = 0; qi < 4; qi++)
            gmax[qi] = fmaxf(fmaxf(red[qi*4+0], red[qi*4+1]),
                             fmaxf(red[qi*4+2], red[qi*4+3]));
        __syncthreads();
    }
    float gsum[4];
    {
        float ls[4] = {0.f, 0.f, 0.f, 0.f};
        #pragma unroll
        for (int mc = 0; mc < 4; mc++)
            #pragma unroll
            for (int qi = 0; qi < 4; qi++) {
                int m = mc*128 + tid;
                float e = expf(sc[qi][m] - gmax[qi]);
                sc[qi][m] = e;
                ls[qi] += e;
            }
        #pragma unroll
        for (int o = 16; o > 0; o >>= 1)
            #pragma unroll
            for (int qi = 0; qi < 4; qi++)
                ls[qi] += __shfl_xor_sync(0xffffffffu, ls[qi], o);
        if ((tid & 31) == 0) {
            int w = tid >> 5;
            #pragma unroll
            for (int qi = 0; qi < 4; qi++) red[qi*4 + w] = ls[qi];
        }
        __syncthreads();
        #pragma unroll
        for (int qi = 0; qi < 4; qi++)
            gsum[qi] = red[qi*4+0] + red[qi*4+1] + red[qi*4+2] + red[qi*4+3];
    }
    #pragma unroll
    for (int qi = 0; qi < 4; qi++) {
        float inv = 1.0f / gsum[qi];
        #pragma unroll
        for (int mc = 0; mc < 4; mc++) {
            int m = mc*128 + tid;
            float p = sc[qi][m] * inv;
            sc[qi][m] = p;
            atomicAdd(&pbin[qi][myidx[qi][mc]], p);
        }
    }
    __syncthreads();

    // ---- phase 3: attn @ v ----
    const int d   = tid & 63;
    const int par = tid >> 6;
    float acc[4] = {0.f, 0.f, 0.f, 0.f};
    for (int mc = 0; mc < 4; mc++) {
        const float* vbase = g_v + ((size_t)(b*Nn + mc*128))*Dd + h*DHd;
        for (int i = tid; i < 128*64; i += 128) {
            int r = i >> 6, c = i & 63;
            ks[r][c] = vbase[(size_t)r*Dd + c];
        }
        __syncthreads();
        for (int ml = par; ml < 128; ml += 2) {
            float vv = ks[ml][d];
            #pragma unroll
            for (int qi = 0; qi < 4; qi++) acc[qi] += sc[qi][mc*128 + ml] * vv;
        }
        __syncthreads();
    }
    #pragma unroll
    for (int qi = 0; qi < 4; qi++) part[par][qi][d] = acc[qi];
    __syncthreads();

    if (tid < 64) {
        #pragma unroll
        for (int qi = 0; qi < 4; qi++) {
            float od = part[0][qi][tid] + part[1][qi][tid];
            #pragma unroll
            for (int j = 0; j < Kb; j++) od += pbin[qi][j] * relv[j*DHd + tid];
            g_o[((size_t)(b*Nn + n0 + qi))*Dd + h*DHd + tid] = od;
        }
    }
}

// ---------------- fp32 SGEMM: C = A@B + bias (+res) (+gelu) -----------------
// 64x64 tile, BK=16, 256 threads, 4x4 per thread.
__global__ void sgemm_kernel(const float* __restrict__ A,
                             const float* __restrict__ Bm,
                             const float* __restrict__ bias,
                             const float* __restrict__ res,
                             float* __restrict__ C,
                             int Mr, int Nc, int Kc, int doGelu) {
    __shared__ __align__(16) float As[16][68];
    __shared__ __align__(16) float Bs[16][64];
    const int tx = threadIdx.x & 15;
    const int ty = threadIdx.x >> 4;
    const int m0 = blockIdx.y * 64;
    const int n0 = blockIdx.x * 64;

    float acc[4][4] = {};
    for (int k0 = 0; k0 < Kc; k0 += 16) {
        {
            int i  = threadIdx.x * 4;
            int mr = i >> 4, kc = i & 15;
            float4 av = *(const float4*)&A[(size_t)(m0 + mr)*Kc + k0 + kc];
            As[kc+0][mr] = av.x; As[kc+1][mr] = av.y;
            As[kc+2][mr] = av.z; As[kc+3][mr] = av.w;
            int r = i >> 6, c = i & 63;
            *(float4*)&Bs[r][c] = *(const float4*)&Bm[(size_t)(k0 + r)*Nc + n0 + c];
        }
        __syncthreads();
        #pragma unroll
        for (int kk = 0; kk < 16; kk++) {
            float4 a  = *(const float4*)&As[kk][ty*4];
            float4 bv = *(const float4*)&Bs[kk][tx*4];
            float ar[4] = {a.x, a.y, a.z, a.w};
            float br[4] = {bv.x, bv.y, bv.z, bv.w};
            #pragma unroll
            for (int i = 0; i < 4; i++)
                #pragma unroll
                for (int j = 0; j < 4; j++)
                    acc[i][j] += ar[i] * br[j];
        }
        __syncthreads();
    }

    #pragma unroll
    for (int i = 0; i < 4; i++) {
        int cm = m0 + ty*4 + i;
        #pragma unroll
        for (int j = 0; j < 4; j++) {
            int cn = n0 + tx*4 + j;
            float val = acc[i][j] + bias[cn];
            if (res)  val += res[(size_t)cm*Nc + cn];
            if (doGelu) val = 0.5f * val * (1.0f + erff(val * 0.70710678118654752f));
            C[(size_t)cm*Nc + cn] = val;
        }
    }
}

// ---------------------------------------------------------------------------
extern "C" void kernel_launch(void* const* d_in, const int* in_sizes, int n_in,
                              void* d_out, int out_size) {
    const float* x     = (const float*)d_in[0];
    const float* coord = (const float*)d_in[1];
    const float* ln1_g = (const float*)d_in[2];
    const float* ln1_b = (const float*)d_in[3];
    const float* wq    = (const float*)d_in[4];
    const float* bq    = (const float*)d_in[5];
    const float* wk    = (const float*)d_in[6];
    const float* bk    = (const float*)d_in[7];
    const float* wv    = (const float*)d_in[8];
    const float* bv    = (const float*)d_in[9];
    const float* wo    = (const float*)d_in[10];
    const float* bo    = (const float*)d_in[11];
    const float* rel_k = (const float*)d_in[12];
    const float* rel_v = (const float*)d_in[13];
    const float* ln2_g = (const float*)d_in[14];
    const float* ln2_b = (const float*)d_in[15];
    const float* w1    = (const float*)d_in[16];
    const float* b1    = (const float*)d_in[17];
    const float* w2    = (const float*)d_in[18];
    const float* b2    = (const float*)d_in[19];
    const float* lnf_g = (const float*)d_in[20];
    const float* lnf_b = (const float*)d_in[21];

    float *px, *ph, *pq, *pk, *pv, *po, *pf;
    cudaGetSymbolAddress((void**)&px, g_x);
    cudaGetSymbolAddress((void**)&ph, g_h);
    cudaGetSymbolAddress((void**)&pq, g_q);
    cudaGetSymbolAddress((void**)&pk, g_k);
    cudaGetSymbolAddress((void**)&pv, g_v);
    cudaGetSymbolAddress((void**)&po, g_o);
    cudaGetSymbolAddress((void**)&pf, g_f);

    cudaMemcpyAsync(px, x, sizeof(float)*TOK*Dd, cudaMemcpyDeviceToDevice);
    idx_kernel<<<dim3(Nn, Bb), Nn>>>(coord);

    const dim3 gProj(Dd/64, TOK/64);   // (8, 32)
    const dim3 gFfn1(Mf/64, TOK/64);   // (32, 32)

    for (int l = 0; l < Ll; l++) {
        ln_kernel<<<TOK, 256>>>(px, ln1_g + l*Dd, ln1_b + l*Dd, ph);
        sgemm_kernel<<<gProj, 256>>>(ph, wq + (size_t)l*Dd*Dd, bq + l*Dd, nullptr, pq, TOK, Dd, Dd, 0);
        sgemm_kernel<<<gProj, 256>>>(ph, wk + (size_t)l*Dd*Dd, bk + l*Dd, nullptr, pk, TOK, Dd, Dd, 0);
        sgemm_kernel<<<gProj, 256>>>(ph, wv + (size_t)l*Dd*Dd, bv + l*Dd, nullptr, pv, TOK, Dd, Dd, 0);
        qrel_kernel<<<(TOK*Hh*Kb + 255)/256, 256>>>(rel_k + (size_t)l*Kb*DHd);
        attn_kernel<<<dim3(Nn/4, Hh, Bb), 128>>>(rel_v + (size_t)l*Kb*DHd);
        sgemm_kernel<<<gProj, 256>>>(po, wo + (size_t)l*Dd*Dd, bo + l*Dd, px, px, TOK, Dd, Dd, 0);
        ln_kernel<<<TOK, 256>>>(px, ln2_g + l*Dd, ln2_b + l*Dd, ph);
        sgemm_kernel<<<gFfn1, 256>>>(ph, w1 + (size_t)l*Dd*Mf, b1 + l*Mf, nullptr, pf, TOK, Mf, Dd, 1);
        sgemm_kernel<<<gProj, 256>>>(pf, w2 + (size_t)l*Mf*Dd, b2 + l*Dd, px, px, TOK, Dd, Mf, 0);
    }
    ln_kernel<<<TOK, 256>>>(px, lnf_g, lnf_b, (float*)d_out);
}

// round 5
// speedup vs baseline: 1.1816x; 1.1816x over previous
#include <cuda_runtime.h>
#include <cuda_bf16.h>
#include <cstdint>
#include <math.h>

// Problem constants
#define Bb   4
#define Nn   512
#define Dd   512
#define Hh   8
#define DHd  64
#define Kb   10
#define Mf   2048
#define Ll   4
#define TOK  (Bb*Nn)      // 2048
#define EPSf 1e-5f

// ---------------- scratch (device globals: no allocations allowed) ----------
__device__ float g_x[TOK*Dd];
__device__ float g_h[TOK*Dd];
__device__ float g_q[TOK*Dd];
__device__ float g_k[TOK*Dd];
__device__ float g_v[TOK*Dd];
__device__ float g_o[TOK*Dd];
__device__ float g_f[TOK*Mf];
__device__ float g_qrel[TOK*Hh*Kb];
__device__ int   g_idx[Bb*Nn*Nn];
// per-layer transposed+split weights [n][k] bf16:
// Wq 512x512 @0 | Wk @262144 | Wv @524288 | Wo @786432 | W1 2048x512 @1048576 | W2 512x2048 @2097152
#define WL_STRIDE 3145728
__device__ __nv_bfloat16 g_whi[Ll*WL_STRIDE];
__device__ __nv_bfloat16 g_wlo[Ll*WL_STRIDE];

// ---------------- mma.sync m16n8k16 bf16 (baseline PTX, sm_80+) -------------
__device__ __forceinline__ void mma16816(float* c, const uint32_t* a, const uint32_t* b) {
    asm volatile("mma.sync.aligned.m16n8k16.row.col.f32.bf16.bf16.f32 "
        "{%0,%1,%2,%3}, {%4,%5,%6,%7}, {%8,%9}, {%0,%1,%2,%3};"
        : "+f"(c[0]), "+f"(c[1]), "+f"(c[2]), "+f"(c[3])
        : "r"(a[0]), "r"(a[1]), "r"(a[2]), "r"(a[3]), "r"(b[0]), "r"(b[1]));
}

// ---------------- distance bins ----------------------------------------------
__global__ void idx_kernel(const float* __restrict__ coord) {
    int n = blockIdx.x, b = blockIdx.y, m = threadIdx.x;
    float2 cn = ((const float2*)coord)[b*Nn + n];
    float2 cm = ((const float2*)coord)[b*Nn + m];
    float dx = cn.x - cm.x, dy = cn.y - cm.y;
    float dist = sqrtf(dx*dx + dy*dy);
    int j = (int)floorf(dist);
    j = j < 0 ? 0 : (j > Kb-1 ? Kb-1 : j);
    g_idx[((size_t)(b*Nn + n))*Nn + m] = j;
}

// ---------------- weight transpose + bf16 hi/lo split ------------------------
// in: W[K][N] fp32 row-major; out: hi/lo[n][k] bf16
__global__ void wconv_kernel(const float* __restrict__ W,
                             __nv_bfloat16* __restrict__ hi,
                             __nv_bfloat16* __restrict__ lo, int K, int N) {
    __shared__ float t[32][33];
    int k0 = blockIdx.y*32, nn0 = blockIdx.x*32;
    int tx = threadIdx.x, ty = threadIdx.y;   // 32 x 8
    #pragma unroll
    for (int i = 0; i < 4; i++) {
        int r = ty + i*8;
        t[r][tx] = W[(size_t)(k0 + r)*N + nn0 + tx];
    }
    __syncthreads();
    #pragma unroll
    for (int i = 0; i < 4; i++) {
        int nl = ty + i*8;
        float v = t[tx][nl];
        __nv_bfloat16 hb = __float2bfloat16_rn(v);
        float lf = v - __bfloat162float(hb);
        size_t o = (size_t)(nn0 + nl)*K + k0 + tx;
        hi[o] = hb; lo[o] = __float2bfloat16_rn(lf);
    }
}

// ---------------- layernorm ---------------------------------------------------
__global__ void ln_kernel(const float* __restrict__ x, const float* __restrict__ g,
                          const float* __restrict__ b, float* __restrict__ out) {
    int row = blockIdx.x, tid = threadIdx.x;   // 256
    const float* xr = x + (size_t)row * Dd;
    float v0 = xr[tid], v1 = xr[tid + 256];
    __shared__ float red[8];
    float s = v0 + v1;
    #pragma unroll
    for (int o = 16; o > 0; o >>= 1) s += __shfl_xor_sync(~0u, s, o);
    if ((tid & 31) == 0) red[tid >> 5] = s;
    __syncthreads();
    float tot = 0.f;
    #pragma unroll
    for (int i = 0; i < 8; i++) tot += red[i];
    float mean = tot * (1.0f / Dd);
    __syncthreads();
    float d0 = v0 - mean, d1 = v1 - mean;
    float vs = d0*d0 + d1*d1;
    #pragma unroll
    for (int o = 16; o > 0; o >>= 1) vs += __shfl_xor_sync(~0u, vs, o);
    if ((tid & 31) == 0) red[tid >> 5] = vs;
    __syncthreads();
    float vt = 0.f;
    #pragma unroll
    for (int i = 0; i < 8; i++) vt += red[i];
    float inv = rsqrtf(vt * (1.0f / Dd) + EPSf);
    out[(size_t)row*Dd + tid]       = d0 * inv * g[tid]       + b[tid];
    out[(size_t)row*Dd + tid + 256] = d1 * inv * g[tid + 256] + b[tid + 256];
}

// ---------------- qrel ---------------------------------------------------------
__global__ void qrel_kernel(const float* __restrict__ relk) {
    int t = blockIdx.x * blockDim.x + threadIdx.x;
    if (t >= TOK*Hh*Kb) return;
    int j = t % Kb, h = (t / Kb) % Hh, tok = t / (Kb * Hh);
    const float* qrow = g_q + (size_t)tok*Dd + h*DHd;
    const float* rk   = relk + j*DHd;
    float dot = 0.f;
    #pragma unroll
    for (int d = 0; d < DHd; d++) dot += qrow[d] * rk[d];
    g_qrel[t] = dot;
}

// ---------------- fused attention (unchanged from passing R3) -----------------
__global__ void attn_kernel(const float* __restrict__ relv) {
    const int n0 = blockIdx.x * 4;
    const int h  = blockIdx.y;
    const int b  = blockIdx.z;
    const int tid = threadIdx.x;   // 128

    __shared__ __align__(16) float ks[128][65];
    __shared__ float sc[4][512];
    __shared__ float qs[4][64];
    __shared__ float qrs[4][Kb];
    __shared__ float pbin[4][Kb];
    __shared__ float part[2][4][64];
    __shared__ float red[16];

    for (int i = tid; i < 4*64; i += 128) {
        int qi = i >> 6, d = i & 63;
        qs[qi][d] = g_q[((size_t)(b*Nn + n0 + qi))*Dd + h*DHd + d];
    }
    if (tid < 4*Kb) {
        int qi = tid / Kb, j = tid % Kb;
        qrs[qi][j]  = g_qrel[(((size_t)(b*Nn + n0 + qi))*Hh + h)*Kb + j];
        pbin[qi][j] = 0.f;
    }
    __syncthreads();

    int myidx[4][4];
    for (int mc = 0; mc < 4; mc++) {
        const float* kbase = g_k + ((size_t)(b*Nn + mc*128))*Dd + h*DHd;
        for (int i = tid; i < 128*64; i += 128) {
            int r = i >> 6, c = i & 63;
            ks[r][c] = kbase[(size_t)r*Dd + c];
        }
        __syncthreads();
        int m = mc*128 + tid;
        float dot[4] = {0.f, 0.f, 0.f, 0.f};
        #pragma unroll
        for (int d = 0; d < 64; d++) {
            float kv = ks[tid][d];
            #pragma unroll
            for (int qi = 0; qi < 4; qi++) dot[qi] += qs[qi][d] * kv;
        }
        #pragma unroll
        for (int qi = 0; qi < 4; qi++) {
            int ji = g_idx[((size_t)(b*Nn + n0 + qi))*Nn + m];
            myidx[qi][mc] = ji;
            sc[qi][m] = (dot[qi] + qrs[qi][ji]) * 0.125f;
        }
        __syncthreads();
    }

    float gmax[4];
    {
        float lm[4];
        #pragma unroll
        for (int qi = 0; qi < 4; qi++) {
            float v = -1e30f;
            #pragma unroll
            for (int mc = 0; mc < 4; mc++) v = fmaxf(v, sc[qi][mc*128 + tid]);
            lm[qi] = v;
        }
        #pragma unroll
        for (int o = 16; o > 0; o >>= 1)
            #pragma unroll
            for (int qi = 0; qi < 4; qi++)
                lm[qi] = fmaxf(lm[qi], __shfl_xor_sync(~0u, lm[qi], o));
        if ((tid & 31) == 0) {
            int w = tid >> 5;
            #pragma unroll
            for (int qi = 0; qi < 4; qi++) red[qi*4 + w] = lm[qi];
        }
        __syncthreads();
        #pragma unroll
        for (int qi = 0; qi < 4; qi++)
            gmax[qi] = fmaxf(fmaxf(red[qi*4+0], red[qi*4+1]),
                             fmaxf(red[qi*4+2], red[qi*4+3]));
        __syncthreads();
    }
    float gsum[4];
    {
        float ls[4] = {0.f, 0.f, 0.f, 0.f};
        #pragma unroll
        for (int mc = 0; mc < 4; mc++)
            #pragma unroll
            for (int qi = 0; qi < 4; qi++) {
                int m = mc*128 + tid;
                float e = expf(sc[qi][m] - gmax[qi]);
                sc[qi][m] = e;
                ls[qi] += e;
            }
        #pragma unroll
        for (int o = 16; o > 0; o >>= 1)
            #pragma unroll
            for (int qi = 0; qi < 4; qi++)
                ls[qi] += __shfl_xor_sync(~0u, ls[qi], o);
        if ((tid & 31) == 0) {
            int w = tid >> 5;
            #pragma unroll
            for (int qi = 0; qi < 4; qi++) red[qi*4 + w] = ls[qi];
        }
        __syncthreads();
        #pragma unroll
        for (int qi = 0; qi < 4; qi++)
            gsum[qi] = red[qi*4+0] + red[qi*4+1] + red[qi*4+2] + red[qi*4+3];
    }
    #pragma unroll
    for (int qi = 0; qi < 4; qi++) {
        float inv = 1.0f / gsum[qi];
        #pragma unroll
        for (int mc = 0; mc < 4; mc++) {
            int m = mc*128 + tid;
            float p = sc[qi][m] * inv;
            sc[qi][m] = p;
            atomicAdd(&pbin[qi][myidx[qi][mc]], p);
        }
    }
    __syncthreads();

    const int d   = tid & 63;
    const int par = tid >> 6;
    float acc[4] = {0.f, 0.f, 0.f, 0.f};
    for (int mc = 0; mc < 4; mc++) {
        const float* vbase = g_v + ((size_t)(b*Nn + mc*128))*Dd + h*DHd;
        for (int i = tid; i < 128*64; i += 128) {
            int r = i >> 6, c = i & 63;
            ks[r][c] = vbase[(size_t)r*Dd + c];
        }
        __syncthreads();
        for (int ml = par; ml < 128; ml += 2) {
            float vv = ks[ml][d];
            #pragma unroll
            for (int qi = 0; qi < 4; qi++) acc[qi] += sc[qi][mc*128 + ml] * vv;
        }
        __syncthreads();
    }
    #pragma unroll
    for (int qi = 0; qi < 4; qi++) part[par][qi][d] = acc[qi];
    __syncthreads();

    if (tid < 64) {
        #pragma unroll
        for (int qi = 0; qi < 4; qi++) {
            float od = part[0][qi][tid] + part[1][qi][tid];
            #pragma unroll
            for (int j = 0; j < Kb; j++) od += pbin[qi][j] * relv[j*DHd + tid];
            g_o[((size_t)(b*Nn + n0 + qi))*Dd + h*DHd + tid] = od;
        }
    }
}

// ---------------- bf16x3 mma.sync GEMM: C = A@W^T + bias (+res)(+gelu) -------
// CTA 128x128, 8 warps (2x4), warp tile 64x32, BK=32.
// A fp32 split to bf16 hi/lo in-kernel; W pre-split [n][k].
// smem stride 40 elems -> conflict-free fragment LDS.
#define SSTR 40
__global__ __launch_bounds__(256) void gemm_mma_kernel(
    const float* __restrict__ A,
    const __nv_bfloat16* __restrict__ Whi, const __nv_bfloat16* __restrict__ Wlo,
    const float* __restrict__ bias, const float* __restrict__ res,
    float* __restrict__ C, int Nc, int Kc, int doGelu) {
    __shared__ __align__(16) __nv_bfloat16 sAhi[128*SSTR];
    __shared__ __align__(16) __nv_bfloat16 sAlo[128*SSTR];
    __shared__ __align__(16) __nv_bfloat16 sBhi[128*SSTR];
    __shared__ __align__(16) __nv_bfloat16 sBlo[128*SSTR];

    const int tid  = threadIdx.x;
    const int wid  = tid >> 5, lane = tid & 31;
    const int wm   = (wid >> 2) * 64;       // warp row offset in CTA tile
    const int wn   = (wid & 3) * 32;        // warp col offset
    const int g    = lane >> 2, t2 = (lane & 3) * 2;
    const int m0   = blockIdx.y * 128, n0 = blockIdx.x * 128;

    float acc[4][4][4] = {};

    for (int kc = 0; kc < Kc; kc += 32) {
        // ---- load A 128x32 fp32 -> hi/lo bf16 ----
        #pragma unroll
        for (int it = 0; it < 4; it++) {
            int idx = tid + it*256;          // 1024 float4s
            int r = idx >> 3, c4 = (idx & 7) << 2;
            float4 v = *(const float4*)&A[(size_t)(m0 + r)*Kc + kc + c4];
            __nv_bfloat16 h0 = __float2bfloat16_rn(v.x), h1 = __float2bfloat16_rn(v.y);
            __nv_bfloat16 h2 = __float2bfloat16_rn(v.z), h3 = __float2bfloat16_rn(v.w);
            __nv_bfloat16 l0 = __float2bfloat16_rn(v.x - __bfloat162float(h0));
            __nv_bfloat16 l1 = __float2bfloat16_rn(v.y - __bfloat162float(h1));
            __nv_bfloat16 l2 = __float2bfloat16_rn(v.z - __bfloat162float(h2));
            __nv_bfloat16 l3 = __float2bfloat16_rn(v.w - __bfloat162float(h3));
            __nv_bfloat162 hp0(h0, h1), hp1(h2, h3), lp0(l0, l1), lp1(l2, l3);
            uint2 uh = { *(uint32_t*)&hp0, *(uint32_t*)&hp1 };
            uint2 ul = { *(uint32_t*)&lp0, *(uint32_t*)&lp1 };
            *(uint2*)&sAhi[r*SSTR + c4] = uh;
            *(uint2*)&sAlo[r*SSTR + c4] = ul;
        }
        // ---- load B (pre-split) 128x32 bf16 hi/lo ----
        #pragma unroll
        for (int it = 0; it < 2; it++) {
            int idx = tid + it*256;          // 512 uint4s
            int r = idx >> 2, q = (idx & 3) << 3;
            const char* ph = (const char*)(Whi + (size_t)(n0 + r)*Kc + kc + q);
            const char* pl = (const char*)(Wlo + (size_t)(n0 + r)*Kc + kc + q);
            *(uint4*)&sBhi[r*SSTR + q] = *(const uint4*)ph;
            *(uint4*)&sBlo[r*SSTR + q] = *(const uint4*)pl;
        }
        __syncthreads();

        #pragma unroll
        for (int ks = 0; ks < 32; ks += 16) {
            uint32_t ah[4][4], al[4][4], bh[4][2], bl[4][2];
            #pragma unroll
            for (int i = 0; i < 4; i++) {
                int r = wm + i*16 + g;
                ah[i][0] = *(uint32_t*)&sAhi[r*SSTR + ks + t2];
                ah[i][1] = *(uint32_t*)&sAhi[(r+8)*SSTR + ks + t2];
                ah[i][2] = *(uint32_t*)&sAhi[r*SSTR + ks + t2 + 8];
                ah[i][3] = *(uint32_t*)&sAhi[(r+8)*SSTR + ks + t2 + 8];
                al[i][0] = *(uint32_t*)&sAlo[r*SSTR + ks + t2];
                al[i][1] = *(uint32_t*)&sAlo[(r+8)*SSTR + ks + t2];
                al[i][2] = *(uint32_t*)&sAlo[r*SSTR + ks + t2 + 8];
                al[i][3] = *(uint32_t*)&sAlo[(r+8)*SSTR + ks + t2 + 8];
            }
            #pragma unroll
            for (int j = 0; j < 4; j++) {
                int nr = wn + j*8 + g;
                bh[j][0] = *(uint32_t*)&sBhi[nr*SSTR + ks + t2];
                bh[j][1] = *(uint32_t*)&sBhi[nr*SSTR + ks + t2 + 8];
                bl[j][0] = *(uint32_t*)&sBlo[nr*SSTR + ks + t2];
                bl[j][1] = *(uint32_t*)&sBlo[nr*SSTR + ks + t2 + 8];
            }
            #pragma unroll
            for (int i = 0; i < 4; i++)
                #pragma unroll
                for (int j = 0; j < 4; j++) {
                    mma16816(acc[i][j], ah[i], bh[j]);   // hi*hi
                    mma16816(acc[i][j], ah[i], bl[j]);   // hi*lo
                    mma16816(acc[i][j], al[i], bh[j]);   // lo*hi
                }
        }
        __syncthreads();
    }

    // ---- epilogue: frag regs -> gmem with bias/res/gelu ----
    #pragma unroll
    for (int i = 0; i < 4; i++) {
        int r0 = m0 + wm + i*16 + g;
        #pragma unroll
        for (int j = 0; j < 4; j++) {
            int col = n0 + wn + j*8 + t2;
            float b0 = bias[col], b1 = bias[col+1];
            float2 v0 = { acc[i][j][0] + b0, acc[i][j][1] + b1 };
            float2 v1 = { acc[i][j][2] + b0, acc[i][j][3] + b1 };
            if (res) {
                float2 r0v = *(const float2*)&res[(size_t)r0*Nc + col];
                float2 r1v = *(const float2*)&res[(size_t)(r0+8)*Nc + col];
                v0.x += r0v.x; v0.y += r0v.y; v1.x += r1v.x; v1.y += r1v.y;
            }
            if (doGelu) {
                v0.x = 0.5f*v0.x*(1.f + erff(v0.x*0.70710678118654752f));
                v0.y = 0.5f*v0.y*(1.f + erff(v0.y*0.70710678118654752f));
                v1.x = 0.5f*v1.x*(1.f + erff(v1.x*0.70710678118654752f));
                v1.y = 0.5f*v1.y*(1.f + erff(v1.y*0.70710678118654752f));
            }
            *(float2*)&C[(size_t)r0*Nc + col]     = v0;
            *(float2*)&C[(size_t)(r0+8)*Nc + col] = v1;
        }
    }
}

// ---------------------------------------------------------------------------
extern "C" void kernel_launch(void* const* d_in, const int* in_sizes, int n_in,
                              void* d_out, int out_size) {
    const float* x     = (const float*)d_in[0];
    const float* coord = (const float*)d_in[1];
    const float* ln1_g = (const float*)d_in[2];
    const float* ln1_b = (const float*)d_in[3];
    const float* wq    = (const float*)d_in[4];
    const float* bq    = (const float*)d_in[5];
    const float* wk    = (const float*)d_in[6];
    const float* bk    = (const float*)d_in[7];
    const float* wv    = (const float*)d_in[8];
    const float* bv    = (const float*)d_in[9];
    const float* wo    = (const float*)d_in[10];
    const float* bo    = (const float*)d_in[11];
    const float* rel_k = (const float*)d_in[12];
    const float* rel_v = (const float*)d_in[13];
    const float* ln2_g = (const float*)d_in[14];
    const float* ln2_b = (const float*)d_in[15];
    const float* w1    = (const float*)d_in[16];
    const float* b1    = (const float*)d_in[17];
    const float* w2    = (const float*)d_in[18];
    const float* b2    = (const float*)d_in[19];
    const float* lnf_g = (const float*)d_in[20];
    const float* lnf_b = (const float*)d_in[21];

    float *px, *ph, *pq, *pk, *pv, *po, *pf;
    __nv_bfloat16 *phi, *plo;
    cudaGetSymbolAddress((void**)&px, g_x);
    cudaGetSymbolAddress((void**)&ph, g_h);
    cudaGetSymbolAddress((void**)&pq, g_q);
    cudaGetSymbolAddress((void**)&pk, g_k);
    cudaGetSymbolAddress((void**)&pv, g_v);
    cudaGetSymbolAddress((void**)&po, g_o);
    cudaGetSymbolAddress((void**)&pf, g_f);
    cudaGetSymbolAddress((void**)&phi, g_whi);
    cudaGetSymbolAddress((void**)&plo, g_wlo);

    cudaMemcpyAsync(px, x, sizeof(float)*TOK*Dd, cudaMemcpyDeviceToDevice);
    idx_kernel<<<dim3(Nn, Bb), Nn>>>(coord);

    // per-launch weight transpose + split
    const dim3 t32(32, 8);
    for (int l = 0; l < Ll; l++) {
        size_t lo = (size_t)l * WL_STRIDE;
        wconv_kernel<<<dim3(16, 16), t32>>>(wq + (size_t)l*Dd*Dd, phi + lo,           plo + lo,           Dd, Dd);
        wconv_kernel<<<dim3(16, 16), t32>>>(wk + (size_t)l*Dd*Dd, phi + lo + 262144,  plo + lo + 262144,  Dd, Dd);
        wconv_kernel<<<dim3(16, 16), t32>>>(wv + (size_t)l*Dd*Dd, phi + lo + 524288,  plo + lo + 524288,  Dd, Dd);
        wconv_kernel<<<dim3(16, 16), t32>>>(wo + (size_t)l*Dd*Dd, phi + lo + 786432,  plo + lo + 786432,  Dd, Dd);
        wconv_kernel<<<dim3(64, 16), t32>>>(w1 + (size_t)l*Dd*Mf, phi + lo + 1048576, plo + lo + 1048576, Dd, Mf);
        wconv_kernel<<<dim3(16, 64), t32>>>(w2 + (size_t)l*Mf*Dd, phi + lo + 2097152, plo + lo + 2097152, Mf, Dd);
    }

    const dim3 gProj(4, 16);    // N=512
    const dim3 gFfn1(16, 16);   // N=2048

    for (int l = 0; l < Ll; l++) {
        size_t lo = (size_t)l * WL_STRIDE;
        ln_kernel<<<TOK, 256>>>(px, ln1_g + l*Dd, ln1_b + l*Dd, ph);
        gemm_mma_kernel<<<gProj, 256>>>(ph, phi + lo,          plo + lo,          bq + l*Dd, nullptr, pq, 512, 512, 0);
        gemm_mma_kernel<<<gProj, 256>>>(ph, phi + lo + 262144, plo + lo + 262144, bk + l*Dd, nullptr, pk, 512, 512, 0);
        gemm_mma_kernel<<<gProj, 256>>>(ph, phi + lo + 524288, plo + lo + 524288, bv + l*Dd, nullptr, pv, 512, 512, 0);
        qrel_kernel<<<(TOK*Hh*Kb + 255)/256, 256>>>(rel_k + (size_t)l*Kb*DHd);
        attn_kernel<<<dim3(Nn/4, Hh, Bb), 128>>>(rel_v + (size_t)l*Kb*DHd);
        gemm_mma_kernel<<<gProj, 256>>>(po, phi + lo + 786432, plo + lo + 786432, bo + l*Dd, px, px, 512, 512, 0);
        ln_kernel<<<TOK, 256>>>(px, ln2_g + l*Dd, ln2_b + l*Dd, ph);
        gemm_mma_kernel<<<gFfn1, 256>>>(ph, phi + lo + 1048576, plo + lo + 1048576, b1 + l*Mf, nullptr, pf, 2048, 512, 1);
        gemm_mma_kernel<<<gProj, 256>>>(pf, phi + lo + 2097152, plo + lo + 2097152, b2 + l*Dd, px, px, 512, 2048, 0);
    }
    ln_kernel<<<TOK, 256>>>(px, lnf_g, lnf_b, (float*)d_out);
}

// round 6
// speedup vs baseline: 2.6384x; 2.2329x over previous
#include <cuda_runtime.h>
#include <cuda_bf16.h>
#include <cstdint>
#include <math.h>

// Problem constants
#define Bb   4
#define Nn   512
#define Dd   512
#define Hh   8
#define DHd  64
#define Kb   10
#define Mf   2048
#define Ll   4
#define TOK  (Bb*Nn)      // 2048
#define EPSf 1e-5f

// ---------------- scratch (device globals) ----------------------------------
__device__ float g_x[TOK*Dd];
__device__ float g_qkv[TOK*1536];
__device__ float g_qrel[TOK*Hh*Kb];
__device__ int   g_idx[Bb*Nn*Nn];
__device__ __nv_bfloat16 g_hhi[TOK*Dd], g_hlo[TOK*Dd];
__device__ __nv_bfloat16 g_ohi[TOK*Dd], g_olo[TOK*Dd];
__device__ __nv_bfloat16 g_fhi[TOK*Mf], g_flo[TOK*Mf];
// per-layer split weights [n][k]: QKV 1536x512 @0 | WO 512x512 @786432 |
// W1 2048x512 @1048576 | W2 512x2048 @2097152
#define WL_STRIDE 3145728
__device__ __nv_bfloat16 g_whi[Ll*WL_STRIDE], g_wlo[Ll*WL_STRIDE];
__device__ float g_bqkv[Ll*1536];

// ---------------- helpers ----------------------------------------------------
__device__ __forceinline__ uint32_t smem_to_u32(const void* p) {
    uint32_t a;
    asm("{ .reg .u64 t; cvta.to.shared.u64 t, %1; cvt.u32.u64 %0, t; }"
        : "=r"(a) : "l"(p));
    return a;
}
__device__ __forceinline__ void cpa16(void* dst, const void* src) {
    uint32_t d = smem_to_u32(dst);
    asm volatile("cp.async.cg.shared.global [%0], [%1], 16;" :: "r"(d), "l"(src));
}
#define CP_COMMIT() asm volatile("cp.async.commit_group;" ::: "memory")
#define CP_WAIT(n)  asm volatile("cp.async.wait_group %0;" :: "n"(n) : "memory")

__device__ __forceinline__ void mma16816(float* c, const uint32_t* a, const uint32_t* b) {
    asm volatile("mma.sync.aligned.m16n8k16.row.col.f32.bf16.bf16.f32 "
        "{%0,%1,%2,%3}, {%4,%5,%6,%7}, {%8,%9}, {%0,%1,%2,%3};"
        : "+f"(c[0]), "+f"(c[1]), "+f"(c[2]), "+f"(c[3])
        : "r"(a[0]), "r"(a[1]), "r"(a[2]), "r"(a[3]), "r"(b[0]), "r"(b[1]));
}

// ---------------- distance bins -----------------------------------------------
__global__ void idx_kernel(const float* __restrict__ coord) {
    int n = blockIdx.x, b = blockIdx.y, m = threadIdx.x;
    float2 cn = ((const float2*)coord)[b*Nn + n];
    float2 cm = ((const float2*)coord)[b*Nn + m];
    float dx = cn.x - cm.x, dy = cn.y - cm.y;
    float dist = sqrtf(dx*dx + dy*dy);
    int j = (int)floorf(dist);
    j = j < 0 ? 0 : (j > Kb-1 ? Kb-1 : j);
    g_idx[((size_t)(b*Nn + n))*Nn + m] = j;
}

// ---------------- weight transpose + split ------------------------------------
__global__ void wconv_kernel(const float* __restrict__ W,
                             __nv_bfloat16* __restrict__ hi,
                             __nv_bfloat16* __restrict__ lo, int K, int N) {
    __shared__ float t[32][33];
    int k0 = blockIdx.y*32, nn0 = blockIdx.x*32;
    int tx = threadIdx.x, ty = threadIdx.y;   // 32 x 8
    #pragma unroll
    for (int i = 0; i < 4; i++) {
        int r = ty + i*8;
        t[r][tx] = W[(size_t)(k0 + r)*N + nn0 + tx];
    }
    __syncthreads();
    #pragma unroll
    for (int i = 0; i < 4; i++) {
        int nl = ty + i*8;
        float v = t[tx][nl];
        __nv_bfloat16 hb = __float2bfloat16_rn(v);
        size_t o = (size_t)(nn0 + nl)*K + k0 + tx;
        hi[o] = hb; lo[o] = __float2bfloat16_rn(v - __bfloat162float(hb));
    }
}

__global__ void biaspack_kernel(const float* __restrict__ bq,
                                const float* __restrict__ bk,
                                const float* __restrict__ bv) {
    int i = blockIdx.x*256 + threadIdx.x;
    if (i >= Ll*1536) return;
    int l = i / 1536, c = i % 1536;
    g_bqkv[i] = (c < 512) ? bq[l*512 + c]
              : (c < 1024 ? bk[l*512 + c - 512] : bv[l*512 + c - 1024]);
}

// ---------------- layernorm: fp32 in, bf16 hi/lo out (or fp32 for final) ------
__global__ void ln_kernel(const float* __restrict__ x, const float* __restrict__ g,
                          const float* __restrict__ b,
                          __nv_bfloat16* __restrict__ ohi, __nv_bfloat16* __restrict__ olo,
                          float* __restrict__ of) {
    int row = blockIdx.x, tid = threadIdx.x;   // 256
    const float* xr = x + (size_t)row * Dd;
    float v0 = xr[tid], v1 = xr[tid + 256];
    __shared__ float red[8];
    float s = v0 + v1;
    #pragma unroll
    for (int o = 16; o > 0; o >>= 1) s += __shfl_xor_sync(~0u, s, o);
    if ((tid & 31) == 0) red[tid >> 5] = s;
    __syncthreads();
    float tot = 0.f;
    #pragma unroll
    for (int i = 0; i < 8; i++) tot += red[i];
    float mean = tot * (1.0f / Dd);
    __syncthreads();
    float d0 = v0 - mean, d1 = v1 - mean;
    float vs = d0*d0 + d1*d1;
    #pragma unroll
    for (int o = 16; o > 0; o >>= 1) vs += __shfl_xor_sync(~0u, vs, o);
    if ((tid & 31) == 0) red[tid >> 5] = vs;
    __syncthreads();
    float vt = 0.f;
    #pragma unroll
    for (int i = 0; i < 8; i++) vt += red[i];
    float inv = rsqrtf(vt * (1.0f / Dd) + EPSf);
    float y0 = d0 * inv * g[tid]       + b[tid];
    float y1 = d1 * inv * g[tid + 256] + b[tid + 256];
    if (of) {
        of[(size_t)row*Dd + tid]       = y0;
        of[(size_t)row*Dd + tid + 256] = y1;
    } else {
        __nv_bfloat16 h0 = __float2bfloat16_rn(y0), h1 = __float2bfloat16_rn(y1);
        ohi[(size_t)row*Dd + tid]       = h0;
        ohi[(size_t)row*Dd + tid + 256] = h1;
        olo[(size_t)row*Dd + tid]       = __float2bfloat16_rn(y0 - __bfloat162float(h0));
        olo[(size_t)row*Dd + tid + 256] = __float2bfloat16_rn(y1 - __bfloat162float(h1));
    }
}

// ---------------- qrel: q . rel_k (reads Q slice of qkv) ----------------------
__global__ void qrel_kernel(const float* __restrict__ relk) {
    int t = blockIdx.x * blockDim.x + threadIdx.x;
    if (t >= TOK*Hh*Kb) return;
    int j = t % Kb, h = (t / Kb) % Hh, tok = t / (Kb * Hh);
    const float* qrow = g_qkv + (size_t)tok*1536 + h*DHd;
    const float* rk   = relk + j*DHd;
    float dot = 0.f;
    #pragma unroll
    for (int d = 0; d < DHd; d++) dot += qrow[d] * rk[d];
    g_qrel[t] = dot;
}

// ---------------- fused attention: 16 q-rows/block, 256 threads ---------------
// smem: ks[128*65] 33280 | sc[16*512] 32768 | qs 4096 | qrs 1024 | pbin 1024 | rv 2560
#define ASMEM_TOTAL 74752
__global__ __launch_bounds__(256, 2) void attn_kernel(const float* __restrict__ relv) {
    extern __shared__ char smx[];
    float* ks   = (float*)smx;
    float* sc   = (float*)(smx + 33280);
    float* qs   = (float*)(smx + 66048);
    float* qrs  = (float*)(smx + 70144);
    float* pbin = (float*)(smx + 71168);
    float* rv   = (float*)(smx + 72192);
    const int tid = threadIdx.x;
    const int n0 = blockIdx.x*16, h = blockIdx.y, b = blockIdx.z;

    for (int i = tid; i < 16*64; i += 256) {
        int qi = i >> 6, d = i & 63;
        qs[i] = g_qkv[(size_t)(b*Nn + n0 + qi)*1536 + h*DHd + d];
    }
    if (tid < 16*Kb) {
        int qi = tid / Kb, j = tid % Kb;
        qrs[qi*16 + j] = g_qrel[(((size_t)(b*Nn + n0 + qi))*Hh + h)*Kb + j];
    }
    pbin[tid] = 0.f;
    for (int i = tid; i < Kb*DHd; i += 256) rv[i] = relv[i];
    __syncthreads();

    // ---- phase 1: scores ----
    const int ml = tid & 127, qh = tid >> 7;
    for (int mc = 0; mc < 4; mc++) {
        const float* kb = g_qkv + (size_t)(b*Nn + mc*128)*1536 + Dd + h*DHd;
        for (int i = tid; i < 2048; i += 256) {
            int r = i >> 4, c4 = (i & 15) << 2;
            float4 v = *(const float4*)&kb[(size_t)r*1536 + c4];
            float* p = &ks[r*65 + c4];
            p[0] = v.x; p[1] = v.y; p[2] = v.z; p[3] = v.w;
        }
        __syncthreads();
        float dot[8] = {0,0,0,0,0,0,0,0};
        #pragma unroll 4
        for (int d4 = 0; d4 < 64; d4 += 4) {
            float k0 = ks[ml*65 + d4],     k1 = ks[ml*65 + d4 + 1];
            float k2 = ks[ml*65 + d4 + 2], k3 = ks[ml*65 + d4 + 3];
            #pragma unroll
            for (int qq = 0; qq < 8; qq++) {
                float4 qv = *(float4*)&qs[(qh*8 + qq)*64 + d4];
                dot[qq] += qv.x*k0 + qv.y*k1 + qv.z*k2 + qv.w*k3;
            }
        }
        int m = mc*128 + ml;
        #pragma unroll
        for (int qq = 0; qq < 8; qq++) {
            int qi = qh*8 + qq;
            int ji = g_idx[((size_t)(b*Nn + n0 + qi))*Nn + m];
            sc[qi*512 + m] = (dot[qq] + qrs[qi*16 + ji]) * 0.125f;
        }
        __syncthreads();
    }

    // ---- phase 2: softmax (warp per 2 rows) + register bin mass ----
    const int wid = tid >> 5, lane = tid & 31;
    #pragma unroll
    for (int rr = 0; rr < 2; rr++) {
        int row = wid*2 + rr;
        float mx = -1e30f;
        for (int m = lane; m < 512; m += 32) mx = fmaxf(mx, sc[row*512 + m]);
        #pragma unroll
        for (int o = 16; o > 0; o >>= 1) mx = fmaxf(mx, __shfl_xor_sync(~0u, mx, o));
        float sum = 0.f;
        for (int m = lane; m < 512; m += 32) {
            float e = expf(sc[row*512 + m] - mx);
            sc[row*512 + m] = e; sum += e;
        }
        #pragma unroll
        for (int o = 16; o > 0; o >>= 1) sum += __shfl_xor_sync(~0u, sum, o);
        float inv = 1.f / sum;
        float pb[Kb];
        #pragma unroll
        for (int j = 0; j < Kb; j++) pb[j] = 0.f;
        const int* ir = g_idx + ((size_t)(b*Nn + n0 + row))*Nn;
        for (int m = lane; m < 512; m += 32) {
            float p = sc[row*512 + m] * inv;
            sc[row*512 + m] = p;
            int ji = ir[m];
            #pragma unroll
            for (int j = 0; j < Kb; j++) if (ji == j) pb[j] += p;
        }
        #pragma unroll
        for (int j = 0; j < Kb; j++) {
            float v = pb[j];
            #pragma unroll
            for (int o = 16; o > 0; o >>= 1) v += __shfl_xor_sync(~0u, v, o);
            if (lane == 0) pbin[row*16 + j] = v;
        }
    }
    __syncthreads();

    // ---- phase 3: attn @ v ----
    const int d = tid & 63, s = tid >> 6;
    float acc[4] = {0,0,0,0};
    for (int mc = 0; mc < 4; mc++) {
        const float* vb = g_qkv + (size_t)(b*Nn + mc*128)*1536 + 2*Dd + h*DHd;
        for (int i = tid; i < 2048; i += 256) {
            int r = i >> 4, c4 = (i & 15) << 2;
            float4 v = *(const float4*)&vb[(size_t)r*1536 + c4];
            float* p = &ks[r*65 + c4];
            p[0] = v.x; p[1] = v.y; p[2] = v.z; p[3] = v.w;
        }
        __syncthreads();
        #pragma unroll 4
        for (int m4 = 0; m4 < 128; m4 += 4) {
            float v0 = ks[(m4+0)*65 + d], v1 = ks[(m4+1)*65 + d];
            float v2 = ks[(m4+2)*65 + d], v3 = ks[(m4+3)*65 + d];
            #pragma unroll
            for (int qq = 0; qq < 4; qq++) {
                float4 p = *(float4*)&sc[(s*4 + qq)*512 + mc*128 + m4];
                acc[qq] += p.x*v0 + p.y*v1 + p.z*v2 + p.w*v3;
            }
        }
        __syncthreads();
    }
    #pragma unroll
    for (int qq = 0; qq < 4; qq++) {
        int qi = s*4 + qq;
        float o = acc[qq];
        #pragma unroll
        for (int j = 0; j < Kb; j++) o += pbin[qi*16 + j] * rv[j*64 + d];
        size_t tok = (size_t)(b*Nn + n0 + qi);
        __nv_bfloat16 hb = __float2bfloat16_rn(o);
        g_ohi[tok*Dd + h*DHd + d] = hb;
        g_olo[tok*Dd + h*DHd + d] = __float2bfloat16_rn(o - __bfloat162float(hb));
    }
}

// ---------------- bf16x3 mma GEMM, double-buffered cp.async -------------------
// CTA 64(M)x128(N), BK=32, 256 thr, 8 warps 2x4 (warp 32x32).
// A, B both pre-split bf16 [m][k]/[n][k]. Epilogue: bias (+res) (+gelu),
// output fp32 (Cf) or bf16 hi/lo split (Chi/Clo).
#define SSTR 40
#define GSMEM_TOTAL 61440
__global__ __launch_bounds__(256, 2) void gemm_mma_kernel(
    const __nv_bfloat16* __restrict__ Ahi, const __nv_bfloat16* __restrict__ Alo,
    const __nv_bfloat16* __restrict__ Bhi, const __nv_bfloat16* __restrict__ Blo,
    const float* __restrict__ bias, const float* __restrict__ res,
    float* __restrict__ Cf, __nv_bfloat16* __restrict__ Chi, __nv_bfloat16* __restrict__ Clo,
    int Nc, int Kc, int doGelu) {
    extern __shared__ char smx[];
    __nv_bfloat16* sAhi = (__nv_bfloat16*)smx;       // [2][64*SSTR]
    __nv_bfloat16* sAlo = sAhi + 2*64*SSTR;
    __nv_bfloat16* sBhi = sAlo + 2*64*SSTR;          // [2][128*SSTR]
    __nv_bfloat16* sBlo = sBhi + 2*128*SSTR;

    const int tid = threadIdx.x, wid = tid >> 5, lane = tid & 31;
    const int g = lane >> 2, t2 = (lane & 3)*2;
    const int wm = (wid >> 2)*32, wn = (wid & 3)*32;
    const int m0 = blockIdx.y*64, n0 = blockIdx.x*128;

    const int ar = tid >> 2, ac = (tid & 3)*8;        // A: 256 segs
    const int br0 = tid >> 2, bc0 = (tid & 3)*8;      // B: segs tid, tid+256
    const int br1 = (tid + 256) >> 2, bc1 = ((tid + 256) & 3)*8;

    auto issue = [&](int c, int buf) {
        int kc = c*32;
        cpa16(&sAhi[buf*(64*SSTR) + ar*SSTR + ac], Ahi + (size_t)(m0 + ar)*Kc + kc + ac);
        cpa16(&sAlo[buf*(64*SSTR) + ar*SSTR + ac], Alo + (size_t)(m0 + ar)*Kc + kc + ac);
        cpa16(&sBhi[buf*(128*SSTR) + br0*SSTR + bc0], Bhi + (size_t)(n0 + br0)*Kc + kc + bc0);
        cpa16(&sBhi[buf*(128*SSTR) + br1*SSTR + bc1], Bhi + (size_t)(n0 + br1)*Kc + kc + bc1);
        cpa16(&sBlo[buf*(128*SSTR) + br0*SSTR + bc0], Blo + (size_t)(n0 + br0)*Kc + kc + bc0);
        cpa16(&sBlo[buf*(128*SSTR) + br1*SSTR + bc1], Blo + (size_t)(n0 + br1)*Kc + kc + bc1);
    };

    float acc[2][4][4] = {};
    const int nch = Kc >> 5;
    issue(0, 0); CP_COMMIT();

    for (int c = 0; c < nch; c++) {
        int buf = c & 1;
        if (c + 1 < nch) { issue(c + 1, buf ^ 1); CP_COMMIT(); CP_WAIT(1); }
        else             { CP_WAIT(0); }
        __syncthreads();

        const __nv_bfloat16* pAh = sAhi + buf*(64*SSTR);
        const __nv_bfloat16* pAl = sAlo + buf*(64*SSTR);
        const __nv_bfloat16* pBh = sBhi + buf*(128*SSTR);
        const __nv_bfloat16* pBl = sBlo + buf*(128*SSTR);
        #pragma unroll
        for (int ks = 0; ks < 32; ks += 16) {
            uint32_t ah[2][4], al[2][4], bh[4][2], bl[4][2];
            #pragma unroll
            for (int i = 0; i < 2; i++) {
                int rb = (wm + i*16 + g)*SSTR + ks + t2;
                ah[i][0] = *(const uint32_t*)&pAh[rb];
                ah[i][1] = *(const uint32_t*)&pAh[rb + 8*SSTR];
                ah[i][2] = *(const uint32_t*)&pAh[rb + 8];
                ah[i][3] = *(const uint32_t*)&pAh[rb + 8*SSTR + 8];
                al[i][0] = *(const uint32_t*)&pAl[rb];
                al[i][1] = *(const uint32_t*)&pAl[rb + 8*SSTR];
                al[i][2] = *(const uint32_t*)&pAl[rb + 8];
                al[i][3] = *(const uint32_t*)&pAl[rb + 8*SSTR + 8];
            }
            #pragma unroll
            for (int j = 0; j < 4; j++) {
                int nb = (wn + j*8 + g)*SSTR + ks + t2;
                bh[j][0] = *(const uint32_t*)&pBh[nb];
                bh[j][1] = *(const uint32_t*)&pBh[nb + 8];
                bl[j][0] = *(const uint32_t*)&pBl[nb];
                bl[j][1] = *(const uint32_t*)&pBl[nb + 8];
            }
            #pragma unroll
            for (int i = 0; i < 2; i++)
                #pragma unroll
                for (int j = 0; j < 4; j++) {
                    mma16816(acc[i][j], ah[i], bh[j]);
                    mma16816(acc[i][j], ah[i], bl[j]);
                    mma16816(acc[i][j], al[i], bh[j]);
                }
        }
        __syncthreads();
    }

    // ---- epilogue ----
    #pragma unroll
    for (int i = 0; i < 2; i++) {
        int r0 = m0 + wm + i*16 + g;
        #pragma unroll
        for (int j = 0; j < 4; j++) {
            int col = n0 + wn + j*8 + t2;
            float b0 = bias[col], b1 = bias[col + 1];
            float2 v0 = { acc[i][j][0] + b0, acc[i][j][1] + b1 };
            float2 v1 = { acc[i][j][2] + b0, acc[i][j][3] + b1 };
            if (res) {
                float2 r0v = *(const float2*)&res[(size_t)r0*Nc + col];
                float2 r1v = *(const float2*)&res[(size_t)(r0 + 8)*Nc + col];
                v0.x += r0v.x; v0.y += r0v.y; v1.x += r1v.x; v1.y += r1v.y;
            }
            if (doGelu) {
                v0.x = 0.5f*v0.x*(1.f + erff(v0.x*0.70710678118654752f));
                v0.y = 0.5f*v0.y*(1.f + erff(v0.y*0.70710678118654752f));
                v1.x = 0.5f*v1.x*(1.f + erff(v1.x*0.70710678118654752f));
                v1.y = 0.5f*v1.y*(1.f + erff(v1.y*0.70710678118654752f));
            }
            if (Chi) {
                __nv_bfloat16 h00 = __float2bfloat16_rn(v0.x), h01 = __float2bfloat16_rn(v0.y);
                __nv_bfloat16 h10 = __float2bfloat16_rn(v1.x), h11 = __float2bfloat16_rn(v1.y);
                __nv_bfloat162 hp0(h00, h01), hp1(h10, h11);
                __nv_bfloat162 lp0(__float2bfloat16_rn(v0.x - __bfloat162float(h00)),
                                   __float2bfloat16_rn(v0.y - __bfloat162float(h01)));
                __nv_bfloat162 lp1(__float2bfloat16_rn(v1.x - __bfloat162float(h10)),
                                   __float2bfloat16_rn(v1.y - __bfloat162float(h11)));
                *(uint32_t*)&Chi[(size_t)r0*Nc + col]       = *(uint32_t*)&hp0;
                *(uint32_t*)&Chi[(size_t)(r0 + 8)*Nc + col] = *(uint32_t*)&hp1;
                *(uint32_t*)&Clo[(size_t)r0*Nc + col]       = *(uint32_t*)&lp0;
                *(uint32_t*)&Clo[(size_t)(r0 + 8)*Nc + col] = *(uint32_t*)&lp1;
            } else {
                *(float2*)&Cf[(size_t)r0*Nc + col]       = v0;
                *(float2*)&Cf[(size_t)(r0 + 8)*Nc + col] = v1;
            }
        }
    }
}

// ---------------------------------------------------------------------------
extern "C" void kernel_launch(void* const* d_in, const int* in_sizes, int n_in,
                              void* d_out, int out_size) {
    const float* x     = (const float*)d_in[0];
    const float* coord = (const float*)d_in[1];
    const float* ln1_g = (const float*)d_in[2];
    const float* ln1_b = (const float*)d_in[3];
    const float* wq    = (const float*)d_in[4];
    const float* bq    = (const float*)d_in[5];
    const float* wk    = (const float*)d_in[6];
    const float* bk    = (const float*)d_in[7];
    const float* wv    = (const float*)d_in[8];
    const float* bv    = (const float*)d_in[9];
    const float* wo    = (const float*)d_in[10];
    const float* bo    = (const float*)d_in[11];
    const float* rel_k = (const float*)d_in[12];
    const float* rel_v = (const float*)d_in[13];
    const float* ln2_g = (const float*)d_in[14];
    const float* ln2_b = (const float*)d_in[15];
    const float* w1    = (const float*)d_in[16];
    const float* b1    = (const float*)d_in[17];
    const float* w2    = (const float*)d_in[18];
    const float* b2    = (const float*)d_in[19];
    const float* lnf_g = (const float*)d_in[20];
    const float* lnf_b = (const float*)d_in[21];

    float *px, *pqkv, *pbqkv;
    __nv_bfloat16 *phhi, *phlo, *pohi, *polo, *pfhi, *pflo, *pwhi, *pwlo;
    cudaGetSymbolAddress((void**)&px,    g_x);
    cudaGetSymbolAddress((void**)&pqkv,  g_qkv);
    cudaGetSymbolAddress((void**)&pbqkv, g_bqkv);
    cudaGetSymbolAddress((void**)&phhi,  g_hhi);
    cudaGetSymbolAddress((void**)&phlo,  g_hlo);
    cudaGetSymbolAddress((void**)&pohi,  g_ohi);
    cudaGetSymbolAddress((void**)&polo,  g_olo);
    cudaGetSymbolAddress((void**)&pfhi,  g_fhi);
    cudaGetSymbolAddress((void**)&pflo,  g_flo);
    cudaGetSymbolAddress((void**)&pwhi,  g_whi);
    cudaGetSymbolAddress((void**)&pwlo,  g_wlo);

    cudaFuncSetAttribute(gemm_mma_kernel, cudaFuncAttributeMaxDynamicSharedMemorySize, GSMEM_TOTAL);
    cudaFuncSetAttribute(attn_kernel, cudaFuncAttributeMaxDynamicSharedMemorySize, ASMEM_TOTAL);

    cudaMemcpyAsync(px, x, sizeof(float)*TOK*Dd, cudaMemcpyDeviceToDevice);
    idx_kernel<<<dim3(Nn, Bb), Nn>>>(coord);
    biaspack_kernel<<<(Ll*1536 + 255)/256, 256>>>(bq, bk, bv);

    const dim3 t32(32, 8);
    for (int l = 0; l < Ll; l++) {
        size_t lo = (size_t)l * WL_STRIDE;
        wconv_kernel<<<dim3(16, 16), t32>>>(wq + (size_t)l*Dd*Dd, pwhi + lo,           pwlo + lo,           Dd, Dd);
        wconv_kernel<<<dim3(16, 16), t32>>>(wk + (size_t)l*Dd*Dd, pwhi + lo + 262144,  pwlo + lo + 262144,  Dd, Dd);
        wconv_kernel<<<dim3(16, 16), t32>>>(wv + (size_t)l*Dd*Dd, pwhi + lo + 524288,  pwlo + lo + 524288,  Dd, Dd);
        wconv_kernel<<<dim3(16, 16), t32>>>(wo + (size_t)l*Dd*Dd, pwhi + lo + 786432,  pwlo + lo + 786432,  Dd, Dd);
        wconv_kernel<<<dim3(64, 16), t32>>>(w1 + (size_t)l*Dd*Mf, pwhi + lo + 1048576, pwlo + lo + 1048576, Dd, Mf);
        wconv_kernel<<<dim3(16, 64), t32>>>(w2 + (size_t)l*Mf*Dd, pwhi + lo + 2097152, pwlo + lo + 2097152, Mf, Dd);
    }

    const dim3 gQKV(12, 32);   // N=1536
    const dim3 gPRJ(4, 32);    // N=512
    const dim3 gFF1(16, 32);   // N=2048

    for (int l = 0; l < Ll; l++) {
        size_t lo = (size_t)l * WL_STRIDE;
        ln_kernel<<<TOK, 256>>>(px, ln1_g + l*Dd, ln1_b + l*Dd, phhi, phlo, nullptr);
        gemm_mma_kernel<<<gQKV, 256, GSMEM_TOTAL>>>(
            phhi, phlo, pwhi + lo, pwlo + lo, pbqkv + l*1536, nullptr,
            pqkv, nullptr, nullptr, 1536, 512, 0);
        qrel_kernel<<<(TOK*Hh*Kb + 255)/256, 256>>>(rel_k + (size_t)l*Kb*DHd);
        attn_kernel<<<dim3(Nn/16, Hh, Bb), 256, ASMEM_TOTAL>>>(rel_v + (size_t)l*Kb*DHd);
        gemm_mma_kernel<<<gPRJ, 256, GSMEM_TOTAL>>>(
            pohi, polo, pwhi + lo + 786432, pwlo + lo + 786432, bo + l*Dd, px,
            px, nullptr, nullptr, 512, 512, 0);
        ln_kernel<<<TOK, 256>>>(px, ln2_g + l*Dd, ln2_b + l*Dd, phhi, phlo, nullptr);
        gemm_mma_kernel<<<gFF1, 256, GSMEM_TOTAL>>>(
            phhi, phlo, pwhi + lo + 1048576, pwlo + lo + 1048576, b1 + l*Mf, nullptr,
            nullptr, pfhi, pflo, 2048, 512, 1);
        gemm_mma_kernel<<<gPRJ, 256, GSMEM_TOTAL>>>(
            pfhi, pflo, pwhi + lo + 2097152, pwlo + lo + 2097152, b2 + l*Dd, px,
            px, nullptr, nullptr, 512, 2048, 0);
    }
    ln_kernel<<<TOK, 256>>>(px, lnf_g, lnf_b, nullptr, nullptr, (float*)d_out);
}

// round 7
// speedup vs baseline: 2.8323x; 1.0735x over previous
#include <cuda_runtime.h>
#include <cuda_bf16.h>
#include <cstdint>
#include <math.h>

// Problem constants
#define Bb   4
#define Nn   512
#define Dd   512
#define Hh   8
#define DHd  64
#define Kb   10
#define Mf   2048
#define Ll   4
#define TOK  (Bb*Nn)      // 2048
#define EPSf 1e-5f

// ---------------- scratch (device globals) ----------------------------------
__device__ float g_x[TOK*Dd];
__device__ float g_qkv[TOK*1536];
__device__ int   g_idx[Bb*Nn*Nn];
__device__ __nv_bfloat16 g_hhi[TOK*Dd], g_hlo[TOK*Dd];
__device__ __nv_bfloat16 g_ohi[TOK*Dd], g_olo[TOK*Dd];
__device__ __nv_bfloat16 g_fhi[TOK*Mf], g_flo[TOK*Mf];
// per-layer split weights [n][k]: QKV 1536x512 @0 | WO 512x512 @786432 |
// W1 2048x512 @1048576 | W2 512x2048 @2097152
#define WL_STRIDE 3145728
__device__ __nv_bfloat16 g_whi[Ll*WL_STRIDE], g_wlo[Ll*WL_STRIDE];
__device__ float g_bqkv[Ll*1536];

// ---------------- helpers ----------------------------------------------------
__device__ __forceinline__ uint32_t smem_to_u32(const void* p) {
    uint32_t a;
    asm("{ .reg .u64 t; cvta.to.shared.u64 t, %1; cvt.u32.u64 %0, t; }"
        : "=r"(a) : "l"(p));
    return a;
}
__device__ __forceinline__ void cpa16(void* dst, const void* src) {
    uint32_t d = smem_to_u32(dst);
    asm volatile("cp.async.cg.shared.global [%0], [%1], 16;" :: "r"(d), "l"(src));
}
#define CP_COMMIT() asm volatile("cp.async.commit_group;" ::: "memory")
#define CP_WAIT(n)  asm volatile("cp.async.wait_group %0;" :: "n"(n) : "memory")

__device__ __forceinline__ void mma16816(float* c, const uint32_t* a, const uint32_t* b) {
    asm volatile("mma.sync.aligned.m16n8k16.row.col.f32.bf16.bf16.f32 "
        "{%0,%1,%2,%3}, {%4,%5,%6,%7}, {%8,%9}, {%0,%1,%2,%3};"
        : "+f"(c[0]), "+f"(c[1]), "+f"(c[2]), "+f"(c[3])
        : "r"(a[0]), "r"(a[1]), "r"(a[2]), "r"(a[3]), "r"(b[0]), "r"(b[1]));
}
__device__ __forceinline__ void ldm_x4(uint32_t* r, uint32_t addr) {
    asm volatile("ldmatrix.sync.aligned.m8n8.x4.shared.b16 {%0,%1,%2,%3}, [%4];"
        : "=r"(r[0]), "=r"(r[1]), "=r"(r[2]), "=r"(r[3]) : "r"(addr));
}

// ---------------- distance bins -----------------------------------------------
__global__ void idx_kernel(const float* __restrict__ coord) {
    int n = blockIdx.x, b = blockIdx.y, m = threadIdx.x;
    float2 cn = ((const float2*)coord)[b*Nn + n];
    float2 cm = ((const float2*)coord)[b*Nn + m];
    float dx = cn.x - cm.x, dy = cn.y - cm.y;
    float dist = sqrtf(dx*dx + dy*dy);
    int j = (int)floorf(dist);
    j = j < 0 ? 0 : (j > Kb-1 ? Kb-1 : j);
    g_idx[((size_t)(b*Nn + n))*Nn + m] = j;
}

// ---------------- ALL weight transposes+splits in ONE launch -------------------
// grid (16,16,Ll*6), block (32,8). job t: 0-3 = wq/wk/wv/wo (512x512),
// 4 = w1 (K=512,N=2048, 4 n-reps), 5 = w2 (K=2048,N=512, 4 k-reps).
__global__ void wconv_all_kernel(const float* __restrict__ wq, const float* __restrict__ wk,
                                 const float* __restrict__ wv, const float* __restrict__ wo,
                                 const float* __restrict__ w1, const float* __restrict__ w2) {
    __shared__ float t[32][33];
    int z = blockIdx.z, l = z / 6, job = z % 6;
    const float* W; int K, N; size_t off;
    switch (job) {
        case 0: W = wq + (size_t)l*Dd*Dd; K = 512;  N = 512;  off = 0;       break;
        case 1: W = wk + (size_t)l*Dd*Dd; K = 512;  N = 512;  off = 262144;  break;
        case 2: W = wv + (size_t)l*Dd*Dd; K = 512;  N = 512;  off = 524288;  break;
        case 3: W = wo + (size_t)l*Dd*Dd; K = 512;  N = 512;  off = 786432;  break;
        case 4: W = w1 + (size_t)l*Dd*Mf; K = 512;  N = 2048; off = 1048576; break;
        default:W = w2 + (size_t)l*Mf*Dd; K = 2048; N = 512;  off = 2097152; break;
    }
    __nv_bfloat16* dh = g_whi + (size_t)l*WL_STRIDE + off;
    __nv_bfloat16* dl = g_wlo + (size_t)l*WL_STRIDE + off;
    int reps = (job >= 4) ? 4 : 1;
    int tx = threadIdx.x, ty = threadIdx.y;
    for (int r = 0; r < reps; r++) {
        int nn0, k0;
        if (job == 4)      { nn0 = (blockIdx.x + 16*r)*32; k0 = blockIdx.y*32; }
        else if (job == 5) { nn0 = blockIdx.x*32; k0 = (blockIdx.y + 16*r)*32; }
        else               { nn0 = blockIdx.x*32; k0 = blockIdx.y*32; }
        #pragma unroll
        for (int i = 0; i < 4; i++)
            t[ty + i*8][tx] = W[(size_t)(k0 + ty + i*8)*N + nn0 + tx];
        __syncthreads();
        #pragma unroll
        for (int i = 0; i < 4; i++) {
            int nl = ty + i*8;
            float v = t[tx][nl];
            __nv_bfloat16 hb = __float2bfloat16_rn(v);
            size_t o = (size_t)(nn0 + nl)*K + k0 + tx;
            dh[o] = hb; dl[o] = __float2bfloat16_rn(v - __bfloat162float(hb));
        }
        __syncthreads();
    }
}

__global__ void biaspack_kernel(const float* __restrict__ bq,
                                const float* __restrict__ bk,
                                const float* __restrict__ bv) {
    int i = blockIdx.x*256 + threadIdx.x;
    if (i >= Ll*1536) return;
    int l = i / 1536, c = i % 1536;
    g_bqkv[i] = (c < 512) ? bq[l*512 + c]
              : (c < 1024 ? bk[l*512 + c - 512] : bv[l*512 + c - 1024]);
}

// ---------------- layernorm: warp per row, 8 rows/block ------------------------
__global__ __launch_bounds__(256) void ln_kernel(
    const float* __restrict__ x, const float* __restrict__ g, const float* __restrict__ b,
    __nv_bfloat16* __restrict__ ohi, __nv_bfloat16* __restrict__ olo,
    float* __restrict__ of) {
    int wid = threadIdx.x >> 5, lane = threadIdx.x & 31;
    int row = blockIdx.x*8 + wid;
    const float* xr = x + (size_t)row*Dd;
    float4 v[4];
    float sum = 0.f;
    #pragma unroll
    for (int w = 0; w < 4; w++) {
        v[w] = *(const float4*)&xr[w*128 + lane*4];
        sum += v[w].x + v[w].y + v[w].z + v[w].w;
    }
    #pragma unroll
    for (int o = 16; o > 0; o >>= 1) sum += __shfl_xor_sync(~0u, sum, o);
    float mean = sum * (1.0f / Dd);
    float var = 0.f;
    #pragma unroll
    for (int w = 0; w < 4; w++) {
        v[w].x -= mean; v[w].y -= mean; v[w].z -= mean; v[w].w -= mean;
        var += v[w].x*v[w].x + v[w].y*v[w].y + v[w].z*v[w].z + v[w].w*v[w].w;
    }
    #pragma unroll
    for (int o = 16; o > 0; o >>= 1) var += __shfl_xor_sync(~0u, var, o);
    float inv = rsqrtf(var * (1.0f / Dd) + EPSf);
    #pragma unroll
    for (int w = 0; w < 4; w++) {
        int idx = w*128 + lane*4;
        float4 gg = *(const float4*)&g[idx];
        float4 bb = *(const float4*)&b[idx];
        float y0 = v[w].x*inv*gg.x + bb.x, y1 = v[w].y*inv*gg.y + bb.y;
        float y2 = v[w].z*inv*gg.z + bb.z, y3 = v[w].w*inv*gg.w + bb.w;
        if (of) {
            float4 o4 = {y0, y1, y2, y3};
            *(float4*)&of[(size_t)row*Dd + idx] = o4;
        } else {
            __nv_bfloat16 h0 = __float2bfloat16_rn(y0), h1 = __float2bfloat16_rn(y1);
            __nv_bfloat16 h2 = __float2bfloat16_rn(y2), h3 = __float2bfloat16_rn(y3);
            __nv_bfloat162 hp0(h0, h1), hp1(h2, h3);
            __nv_bfloat162 lp0(__float2bfloat16_rn(y0 - __bfloat162float(h0)),
                               __float2bfloat16_rn(y1 - __bfloat162float(h1)));
            __nv_bfloat162 lp1(__float2bfloat16_rn(y2 - __bfloat162float(h2)),
                               __float2bfloat16_rn(y3 - __bfloat162float(h3)));
            uint2 uh = { *(uint32_t*)&hp0, *(uint32_t*)&hp1 };
            uint2 ul = { *(uint32_t*)&lp0, *(uint32_t*)&lp1 };
            *(uint2*)&ohi[(size_t)row*Dd + idx] = uh;
            *(uint2*)&olo[(size_t)row*Dd + idx] = ul;
        }
    }
}

// ---------------- fused attention (qrel computed in-block) ---------------------
// smem: ks 33280 | sc 32768 | qs 4096 | qrs 1024 | pbin 1024 | rv 2560 | rk 2560
#define ASMEM_TOTAL 77312
__global__ __launch_bounds__(256, 2) void attn_kernel(const float* __restrict__ relk,
                                                      const float* __restrict__ relv) {
    extern __shared__ char smx[];
    float* ks   = (float*)smx;
    float* sc   = (float*)(smx + 33280);
    float* qs   = (float*)(smx + 66048);
    float* qrs  = (float*)(smx + 70144);
    float* pbin = (float*)(smx + 71168);
    float* rv   = (float*)(smx + 72192);
    float* rk   = (float*)(smx + 74752);
    const int tid = threadIdx.x;
    const int n0 = blockIdx.x*16, h = blockIdx.y, b = blockIdx.z;

    for (int i = tid; i < 16*64; i += 256) {
        int qi = i >> 6, d = i & 63;
        qs[i] = g_qkv[(size_t)(b*Nn + n0 + qi)*1536 + h*DHd + d];
    }
    for (int i = tid; i < Kb*DHd; i += 256) { rv[i] = relv[i]; rk[i] = relk[i]; }
    pbin[tid] = 0.f;
    __syncthreads();

    // qrel in-block: 16 rows x 10 bins, dot over 64
    if (tid < 16*Kb) {
        int qi = tid / Kb, j = tid % Kb;
        float dot = 0.f;
        #pragma unroll
        for (int d = 0; d < DHd; d++) dot += qs[qi*64 + d] * rk[j*64 + d];
        qrs[qi*16 + j] = dot;
    }
    __syncthreads();

    // ---- phase 1: scores ----
    const int ml = tid & 127, qh = tid >> 7;
    for (int mc = 0; mc < 4; mc++) {
        const float* kb = g_qkv + (size_t)(b*Nn + mc*128)*1536 + Dd + h*DHd;
        for (int i = tid; i < 2048; i += 256) {
            int r = i >> 4, c4 = (i & 15) << 2;
            float4 v = *(const float4*)&kb[(size_t)r*1536 + c4];
            float* p = &ks[r*65 + c4];
            p[0] = v.x; p[1] = v.y; p[2] = v.z; p[3] = v.w;
        }
        __syncthreads();
        float dot[8] = {0,0,0,0,0,0,0,0};
        #pragma unroll 4
        for (int d4 = 0; d4 < 64; d4 += 4) {
            float k0 = ks[ml*65 + d4],     k1 = ks[ml*65 + d4 + 1];
            float k2 = ks[ml*65 + d4 + 2], k3 = ks[ml*65 + d4 + 3];
            #pragma unroll
            for (int qq = 0; qq < 8; qq++) {
                float4 qv = *(float4*)&qs[(qh*8 + qq)*64 + d4];
                dot[qq] += qv.x*k0 + qv.y*k1 + qv.z*k2 + qv.w*k3;
            }
        }
        int m = mc*128 + ml;
        #pragma unroll
        for (int qq = 0; qq < 8; qq++) {
            int qi = qh*8 + qq;
            int ji = g_idx[((size_t)(b*Nn + n0 + qi))*Nn + m];
            sc[qi*512 + m] = (dot[qq] + qrs[qi*16 + ji]) * 0.125f;
        }
        __syncthreads();
    }

    // ---- phase 2: softmax + register bin mass ----
    const int wid = tid >> 5, lane = tid & 31;
    #pragma unroll
    for (int rr = 0; rr < 2; rr++) {
        int row = wid*2 + rr;
        float mx = -1e30f;
        for (int m = lane; m < 512; m += 32) mx = fmaxf(mx, sc[row*512 + m]);
        #pragma unroll
        for (int o = 16; o > 0; o >>= 1) mx = fmaxf(mx, __shfl_xor_sync(~0u, mx, o));
        float sum = 0.f;
        for (int m = lane; m < 512; m += 32) {
            float e = expf(sc[row*512 + m] - mx);
            sc[row*512 + m] = e; sum += e;
        }
        #pragma unroll
        for (int o = 16; o > 0; o >>= 1) sum += __shfl_xor_sync(~0u, sum, o);
        float inv = 1.f / sum;
        float pb[Kb];
        #pragma unroll
        for (int j = 0; j < Kb; j++) pb[j] = 0.f;
        const int* ir = g_idx + ((size_t)(b*Nn + n0 + row))*Nn;
        for (int m = lane; m < 512; m += 32) {
            float p = sc[row*512 + m] * inv;
            sc[row*512 + m] = p;
            int ji = ir[m];
            #pragma unroll
            for (int j = 0; j < Kb; j++) if (ji == j) pb[j] += p;
        }
        #pragma unroll
        for (int j = 0; j < Kb; j++) {
            float v = pb[j];
            #pragma unroll
            for (int o = 16; o > 0; o >>= 1) v += __shfl_xor_sync(~0u, v, o);
            if (lane == 0) pbin[row*16 + j] = v;
        }
    }
    __syncthreads();

    // ---- phase 3: attn @ v ----
    const int d = tid & 63, s = tid >> 6;
    float acc[4] = {0,0,0,0};
    for (int mc = 0; mc < 4; mc++) {
        const float* vb = g_qkv + (size_t)(b*Nn + mc*128)*1536 + 2*Dd + h*DHd;
        for (int i = tid; i < 2048; i += 256) {
            int r = i >> 4, c4 = (i & 15) << 2;
            float4 v = *(const float4*)&vb[(size_t)r*1536 + c4];
            float* p = &ks[r*65 + c4];
            p[0] = v.x; p[1] = v.y; p[2] = v.z; p[3] = v.w;
        }
        __syncthreads();
        #pragma unroll 4
        for (int m4 = 0; m4 < 128; m4 += 4) {
            float v0 = ks[(m4+0)*65 + d], v1 = ks[(m4+1)*65 + d];
            float v2 = ks[(m4+2)*65 + d], v3 = ks[(m4+3)*65 + d];
            #pragma unroll
            for (int qq = 0; qq < 4; qq++) {
                float4 p = *(float4*)&sc[(s*4 + qq)*512 + mc*128 + m4];
                acc[qq] += p.x*v0 + p.y*v1 + p.z*v2 + p.w*v3;
            }
        }
        __syncthreads();
    }
    #pragma unroll
    for (int qq = 0; qq < 4; qq++) {
        int qi = s*4 + qq;
        float o = acc[qq];
        #pragma unroll
        for (int j = 0; j < Kb; j++) o += pbin[qi*16 + j] * rv[j*64 + d];
        size_t tok = (size_t)(b*Nn + n0 + qi);
        __nv_bfloat16 hb = __float2bfloat16_rn(o);
        g_ohi[tok*Dd + h*DHd + d] = hb;
        g_olo[tok*Dd + h*DHd + d] = __float2bfloat16_rn(o - __bfloat162float(hb));
    }
}

// ---------------- bf16x3 mma GEMM, cp.async double-buffer + ldmatrix ----------
// CTA 64(M)x128(N), BK=32, 256 thr, 8 warps 2x4 (warp 32x32).
#define SSTR 40
#define GSMEM_TOTAL 61440
__global__ __launch_bounds__(256, 2) void gemm_mma_kernel(
    const __nv_bfloat16* __restrict__ Ahi, const __nv_bfloat16* __restrict__ Alo,
    const __nv_bfloat16* __restrict__ Bhi, const __nv_bfloat16* __restrict__ Blo,
    const float* __restrict__ bias, const float* __restrict__ res,
    float* __restrict__ Cf, __nv_bfloat16* __restrict__ Chi, __nv_bfloat16* __restrict__ Clo,
    int Nc, int Kc, int doGelu) {
    extern __shared__ char smx[];
    __nv_bfloat16* sAhi = (__nv_bfloat16*)smx;       // [2][64*SSTR]
    __nv_bfloat16* sAlo = sAhi + 2*64*SSTR;
    __nv_bfloat16* sBhi = sAlo + 2*64*SSTR;          // [2][128*SSTR]
    __nv_bfloat16* sBlo = sBhi + 2*128*SSTR;

    const int tid = threadIdx.x, wid = tid >> 5, lane = tid & 31;
    const int g = lane >> 2, t2 = (lane & 3)*2;
    const int wm = (wid >> 2)*32, wn = (wid & 3)*32;
    const int m0 = blockIdx.y*64, n0 = blockIdx.x*128;

    const int ar = tid >> 2, ac = (tid & 3)*8;
    const int br0 = tid >> 2, bc0 = (tid & 3)*8;
    const int br1 = (tid + 256) >> 2, bc1 = ((tid + 256) & 3)*8;

    // ldmatrix lane-dependent byte offsets
    const int which = lane >> 3, rowin = lane & 7;
    uint32_t aoff[2], boff[2];
    #pragma unroll
    for (int i = 0; i < 2; i++)
        aoff[i] = ((wm + i*16 + (which & 1)*8 + rowin)*SSTR + (which >> 1)*8)*2;
    #pragma unroll
    for (int p = 0; p < 2; p++)
        boff[p] = ((wn + p*16 + (which >> 1)*8 + rowin)*SSTR + (which & 1)*8)*2;
    const uint32_t uAhi = smem_to_u32(sAhi), uAlo = smem_to_u32(sAlo);
    const uint32_t uBhi = smem_to_u32(sBhi), uBlo = smem_to_u32(sBlo);

    auto issue = [&](int c, int buf) {
        int kc = c*32;
        cpa16(&sAhi[buf*(64*SSTR) + ar*SSTR + ac], Ahi + (size_t)(m0 + ar)*Kc + kc + ac);
        cpa16(&sAlo[buf*(64*SSTR) + ar*SSTR + ac], Alo + (size_t)(m0 + ar)*Kc + kc + ac);
        cpa16(&sBhi[buf*(128*SSTR) + br0*SSTR + bc0], Bhi + (size_t)(n0 + br0)*Kc + kc + bc0);
        cpa16(&sBhi[buf*(128*SSTR) + br1*SSTR + bc1], Bhi + (size_t)(n0 + br1)*Kc + kc + bc1);
        cpa16(&sBlo[buf*(128*SSTR) + br0*SSTR + bc0], Blo + (size_t)(n0 + br0)*Kc + kc + bc0);
        cpa16(&sBlo[buf*(128*SSTR) + br1*SSTR + bc1], Blo + (size_t)(n0 + br1)*Kc + kc + bc1);
    };

    float acc[2][4][4] = {};
    const int nch = Kc >> 5;
    issue(0, 0); CP_COMMIT();

    for (int c = 0; c < nch; c++) {
        int buf = c & 1;
        if (c + 1 < nch) { issue(c + 1, buf ^ 1); CP_COMMIT(); CP_WAIT(1); }
        else             { CP_WAIT(0); }
        __syncthreads();

        const uint32_t offA = buf*(64*SSTR*2), offB = buf*(128*SSTR*2);
        #pragma unroll
        for (int ks = 0; ks < 32; ks += 16) {
            uint32_t ah[2][4], al[2][4], bh[8], bl[8];
            #pragma unroll
            for (int i = 0; i < 2; i++) {
                ldm_x4(ah[i], uAhi + offA + aoff[i] + ks*2);
                ldm_x4(al[i], uAlo + offA + aoff[i] + ks*2);
            }
            #pragma unroll
            for (int p = 0; p < 2; p++) {
                ldm_x4(&bh[p*4], uBhi + offB + boff[p] + ks*2);
                ldm_x4(&bl[p*4], uBlo + offB + boff[p] + ks*2);
            }
            #pragma unroll
            for (int i = 0; i < 2; i++)
                #pragma unroll
                for (int j = 0; j < 4; j++) {
                    mma16816(acc[i][j], ah[i], &bh[j*2]);
                    mma16816(acc[i][j], ah[i], &bl[j*2]);
                    mma16816(acc[i][j], al[i], &bh[j*2]);
                }
        }
        __syncthreads();
    }

    // ---- epilogue ----
    #pragma unroll
    for (int i = 0; i < 2; i++) {
        int r0 = m0 + wm + i*16 + g;
        #pragma unroll
        for (int j = 0; j < 4; j++) {
            int col = n0 + wn + j*8 + t2;
            float b0 = bias[col], b1 = bias[col + 1];
            float2 v0 = { acc[i][j][0] + b0, acc[i][j][1] + b1 };
            float2 v1 = { acc[i][j][2] + b0, acc[i][j][3] + b1 };
            if (res) {
                float2 r0v = *(const float2*)&res[(size_t)r0*Nc + col];
                float2 r1v = *(const float2*)&res[(size_t)(r0 + 8)*Nc + col];
                v0.x += r0v.x; v0.y += r0v.y; v1.x += r1v.x; v1.y += r1v.y;
            }
            if (doGelu) {
                v0.x = 0.5f*v0.x*(1.f + erff(v0.x*0.70710678118654752f));
                v0.y = 0.5f*v0.y*(1.f + erff(v0.y*0.70710678118654752f));
                v1.x = 0.5f*v1.x*(1.f + erff(v1.x*0.70710678118654752f));
                v1.y = 0.5f*v1.y*(1.f + erff(v1.y*0.70710678118654752f));
            }
            if (Chi) {
                __nv_bfloat16 h00 = __float2bfloat16_rn(v0.x), h01 = __float2bfloat16_rn(v0.y);
                __nv_bfloat16 h10 = __float2bfloat16_rn(v1.x), h11 = __float2bfloat16_rn(v1.y);
                __nv_bfloat162 hp0(h00, h01), hp1(h10, h11);
                __nv_bfloat162 lp0(__float2bfloat16_rn(v0.x - __bfloat162float(h00)),
                                   __float2bfloat16_rn(v0.y - __bfloat162float(h01)));
                __nv_bfloat162 lp1(__float2bfloat16_rn(v1.x - __bfloat162float(h10)),
                                   __float2bfloat16_rn(v1.y - __bfloat162float(h11)));
                *(uint32_t*)&Chi[(size_t)r0*Nc + col]       = *(uint32_t*)&hp0;
                *(uint32_t*)&Chi[(size_t)(r0 + 8)*Nc + col] = *(uint32_t*)&hp1;
                *(uint32_t*)&Clo[(size_t)r0*Nc + col]       = *(uint32_t*)&lp0;
                *(uint32_t*)&Clo[(size_t)(r0 + 8)*Nc + col] = *(uint32_t*)&lp1;
            } else {
                *(float2*)&Cf[(size_t)r0*Nc + col]       = v0;
                *(float2*)&Cf[(size_t)(r0 + 8)*Nc + col] = v1;
            }
        }
    }
}

// ---------------------------------------------------------------------------
extern "C" void kernel_launch(void* const* d_in, const int* in_sizes, int n_in,
                              void* d_out, int out_size) {
    const float* x     = (const float*)d_in[0];
    const float* coord = (const float*)d_in[1];
    const float* ln1_g = (const float*)d_in[2];
    const float* ln1_b = (const float*)d_in[3];
    const float* wq    = (const float*)d_in[4];
    const float* bq    = (const float*)d_in[5];
    const float* wk    = (const float*)d_in[6];
    const float* bk    = (const float*)d_in[7];
    const float* wv    = (const float*)d_in[8];
    const float* bv    = (const float*)d_in[9];
    const float* wo    = (const float*)d_in[10];
    const float* bo    = (const float*)d_in[11];
    const float* rel_k = (const float*)d_in[12];
    const float* rel_v = (const float*)d_in[13];
    const float* ln2_g = (const float*)d_in[14];
    const float* ln2_b = (const float*)d_in[15];
    const float* w1    = (const float*)d_in[16];
    const float* b1    = (const float*)d_in[17];
    const float* w2    = (const float*)d_in[18];
    const float* b2    = (const float*)d_in[19];
    const float* lnf_g = (const float*)d_in[20];
    const float* lnf_b = (const float*)d_in[21];

    float *px, *pqkv, *pbqkv;
    __nv_bfloat16 *phhi, *phlo, *pohi, *polo, *pfhi, *pflo, *pwhi, *pwlo;
    cudaGetSymbolAddress((void**)&px,    g_x);
    cudaGetSymbolAddress((void**)&pqkv,  g_qkv);
    cudaGetSymbolAddress((void**)&pbqkv, g_bqkv);
    cudaGetSymbolAddress((void**)&phhi,  g_hhi);
    cudaGetSymbolAddress((void**)&phlo,  g_hlo);
    cudaGetSymbolAddress((void**)&pohi,  g_ohi);
    cudaGetSymbolAddress((void**)&polo,  g_olo);
    cudaGetSymbolAddress((void**)&pfhi,  g_fhi);
    cudaGetSymbolAddress((void**)&pflo,  g_flo);
    cudaGetSymbolAddress((void**)&pwhi,  g_whi);
    cudaGetSymbolAddress((void**)&pwlo,  g_wlo);

    cudaFuncSetAttribute(gemm_mma_kernel, cudaFuncAttributeMaxDynamicSharedMemorySize, GSMEM_TOTAL);
    cudaFuncSetAttribute(attn_kernel, cudaFuncAttributeMaxDynamicSharedMemorySize, ASMEM_TOTAL);

    cudaMemcpyAsync(px, x, sizeof(float)*TOK*Dd, cudaMemcpyDeviceToDevice);
    idx_kernel<<<dim3(Nn, Bb), Nn>>>(coord);
    biaspack_kernel<<<(Ll*1536 + 255)/256, 256>>>(bq, bk, bv);
    wconv_all_kernel<<<dim3(16, 16, Ll*6), dim3(32, 8)>>>(wq, wk, wv, wo, w1, w2);

    const dim3 gQKV(12, 32);   // N=1536
    const dim3 gPRJ(4, 32);    // N=512
    const dim3 gFF1(16, 32);   // N=2048

    for (int l = 0; l < Ll; l++) {
        size_t lo = (size_t)l * WL_STRIDE;
        ln_kernel<<<TOK/8, 256>>>(px, ln1_g + l*Dd, ln1_b + l*Dd, phhi, phlo, nullptr);
        gemm_mma_kernel<<<gQKV, 256, GSMEM_TOTAL>>>(
            phhi, phlo, pwhi + lo, pwlo + lo, pbqkv + l*1536, nullptr,
            pqkv, nullptr, nullptr, 1536, 512, 0);
        attn_kernel<<<dim3(Nn/16, Hh, Bb), 256, ASMEM_TOTAL>>>(
            rel_k + (size_t)l*Kb*DHd, rel_v + (size_t)l*Kb*DHd);
        gemm_mma_kernel<<<gPRJ, 256, GSMEM_TOTAL>>>(
            pohi, polo, pwhi + lo + 786432, pwlo + lo + 786432, bo + l*Dd, px,
            px, nullptr, nullptr, 512, 512, 0);
        ln_kernel<<<TOK/8, 256>>>(px, ln2_g + l*Dd, ln2_b + l*Dd, phhi, phlo, nullptr);
        gemm_mma_kernel<<<gFF1, 256, GSMEM_TOTAL>>>(
            phhi, phlo, pwhi + lo + 1048576, pwlo + lo + 1048576, b1 + l*Mf, nullptr,
            nullptr, pfhi, pflo, 2048, 512, 1);
        gemm_mma_kernel<<<gPRJ, 256, GSMEM_TOTAL>>>(
            pfhi, pflo, pwhi + lo + 2097152, pwlo + lo + 2097152, b2 + l*Dd, px,
            px, nullptr, nullptr, 512, 2048, 0);
    }
    ln_kernel<<<TOK/8, 256>>>(px, lnf_g, lnf_b, nullptr, nullptr, (float*)d_out);
}

// round 8
// speedup vs baseline: 2.9927x; 1.0566x over previous
#include <cuda_runtime.h>
#include <cuda_bf16.h>
#include <cstdint>
#include <math.h>

// Problem constants
#define Bb   4
#define Nn   512
#define Dd   512
#define Hh   8
#define DHd  64
#define Kb   10
#define Mf   2048
#define Ll   4
#define TOK  (Bb*Nn)      // 2048
#define EPSf 1e-5f

// ---------------- scratch (device globals) ----------------------------------
__device__ float g_x[TOK*Dd];
__device__ int   g_idx[Bb*Nn*Nn];
__device__ __nv_bfloat16 g_qkvhi[TOK*1536], g_qkvlo[TOK*1536];
__device__ __nv_bfloat16 g_hhi[TOK*Dd], g_hlo[TOK*Dd];
__device__ __nv_bfloat16 g_ohi[TOK*Dd], g_olo[TOK*Dd];
__device__ __nv_bfloat16 g_fhi[TOK*Mf], g_flo[TOK*Mf];
#define WL_STRIDE 3145728
__device__ __nv_bfloat16 g_whi[Ll*WL_STRIDE], g_wlo[Ll*WL_STRIDE];
__device__ float g_bqkv[Ll*1536];

// ---------------- helpers ----------------------------------------------------
__device__ __forceinline__ uint32_t smem_to_u32(const void* p) {
    uint32_t a;
    asm("{ .reg .u64 t; cvta.to.shared.u64 t, %1; cvt.u32.u64 %0, t; }"
        : "=r"(a) : "l"(p));
    return a;
}
__device__ __forceinline__ void cpa16(void* dst, const void* src) {
    uint32_t d = smem_to_u32(dst);
    asm volatile("cp.async.cg.shared.global [%0], [%1], 16;" :: "r"(d), "l"(src));
}
#define CP_COMMIT() asm volatile("cp.async.commit_group;" ::: "memory")
#define CP_WAIT(n)  asm volatile("cp.async.wait_group %0;" :: "n"(n) : "memory")

__device__ __forceinline__ void mma16816(float* c, const uint32_t* a, const uint32_t* b) {
    asm volatile("mma.sync.aligned.m16n8k16.row.col.f32.bf16.bf16.f32 "
        "{%0,%1,%2,%3}, {%4,%5,%6,%7}, {%8,%9}, {%0,%1,%2,%3};"
        : "+f"(c[0]), "+f"(c[1]), "+f"(c[2]), "+f"(c[3])
        : "r"(a[0]), "r"(a[1]), "r"(a[2]), "r"(a[3]), "r"(b[0]), "r"(b[1]));
}
__device__ __forceinline__ void ldm_x4(uint32_t* r, uint32_t addr) {
    asm volatile("ldmatrix.sync.aligned.m8n8.x4.shared.b16 {%0,%1,%2,%3}, [%4];"
        : "=r"(r[0]), "=r"(r[1]), "=r"(r[2]), "=r"(r[3]) : "r"(addr));
}
__device__ __forceinline__ float bf2f(__nv_bfloat16 h) { return __bfloat162float(h); }

// ---------------- distance bins -----------------------------------------------
__global__ void idx_kernel(const float* __restrict__ coord) {
    int n = blockIdx.x, b = blockIdx.y, m = threadIdx.x;
    float2 cn = ((const float2*)coord)[b*Nn + n];
    float2 cm = ((const float2*)coord)[b*Nn + m];
    float dx = cn.x - cm.x, dy = cn.y - cm.y;
    float dist = sqrtf(dx*dx + dy*dy);
    int j = (int)floorf(dist);
    j = j < 0 ? 0 : (j > Kb-1 ? Kb-1 : j);
    g_idx[((size_t)(b*Nn + n))*Nn + m] = j;
}

// ---------------- ALL weight transposes+splits in ONE launch -------------------
__global__ void wconv_all_kernel(const float* __restrict__ wq, const float* __restrict__ wk,
                                 const float* __restrict__ wv, const float* __restrict__ wo,
                                 const float* __restrict__ w1, const float* __restrict__ w2) {
    __shared__ float t[32][33];
    int z = blockIdx.z, l = z / 6, job = z % 6;
    const float* W; int K, N; size_t off;
    switch (job) {
        case 0: W = wq + (size_t)l*Dd*Dd; K = 512;  N = 512;  off = 0;       break;
        case 1: W = wk + (size_t)l*Dd*Dd; K = 512;  N = 512;  off = 262144;  break;
        case 2: W = wv + (size_t)l*Dd*Dd; K = 512;  N = 512;  off = 524288;  break;
        case 3: W = wo + (size_t)l*Dd*Dd; K = 512;  N = 512;  off = 786432;  break;
        case 4: W = w1 + (size_t)l*Dd*Mf; K = 512;  N = 2048; off = 1048576; break;
        default:W = w2 + (size_t)l*Mf*Dd; K = 2048; N = 512;  off = 2097152; break;
    }
    __nv_bfloat16* dh = g_whi + (size_t)l*WL_STRIDE + off;
    __nv_bfloat16* dl = g_wlo + (size_t)l*WL_STRIDE + off;
    int reps = (job >= 4) ? 4 : 1;
    int tx = threadIdx.x, ty = threadIdx.y;
    for (int r = 0; r < reps; r++) {
        int nn0, k0;
        if (job == 4)      { nn0 = (blockIdx.x + 16*r)*32; k0 = blockIdx.y*32; }
        else if (job == 5) { nn0 = blockIdx.x*32; k0 = (blockIdx.y + 16*r)*32; }
        else               { nn0 = blockIdx.x*32; k0 = blockIdx.y*32; }
        #pragma unroll
        for (int i = 0; i < 4; i++)
            t[ty + i*8][tx] = W[(size_t)(k0 + ty + i*8)*N + nn0 + tx];
        __syncthreads();
        #pragma unroll
        for (int i = 0; i < 4; i++) {
            int nl = ty + i*8;
            float v = t[tx][nl];
            __nv_bfloat16 hb = __float2bfloat16_rn(v);
            size_t o = (size_t)(nn0 + nl)*K + k0 + tx;
            dh[o] = hb; dl[o] = __float2bfloat16_rn(v - bf2f(hb));
        }
        __syncthreads();
    }
}

__global__ void biaspack_kernel(const float* __restrict__ bq,
                                const float* __restrict__ bk,
                                const float* __restrict__ bv) {
    int i = blockIdx.x*256 + threadIdx.x;
    if (i >= Ll*1536) return;
    int l = i / 1536, c = i % 1536;
    g_bqkv[i] = (c < 512) ? bq[l*512 + c]
              : (c < 1024 ? bk[l*512 + c - 512] : bv[l*512 + c - 1024]);
}

// ---------------- layernorm: warp per row, 8 rows/block ------------------------
__global__ __launch_bounds__(256) void ln_kernel(
    const float* __restrict__ x, const float* __restrict__ g, const float* __restrict__ b,
    __nv_bfloat16* __restrict__ ohi, __nv_bfloat16* __restrict__ olo,
    float* __restrict__ of) {
    int wid = threadIdx.x >> 5, lane = threadIdx.x & 31;
    int row = blockIdx.x*8 + wid;
    const float* xr = x + (size_t)row*Dd;
    float4 v[4];
    float sum = 0.f;
    #pragma unroll
    for (int w = 0; w < 4; w++) {
        v[w] = *(const float4*)&xr[w*128 + lane*4];
        sum += v[w].x + v[w].y + v[w].z + v[w].w;
    }
    #pragma unroll
    for (int o = 16; o > 0; o >>= 1) sum += __shfl_xor_sync(~0u, sum, o);
    float mean = sum * (1.0f / Dd);
    float var = 0.f;
    #pragma unroll
    for (int w = 0; w < 4; w++) {
        v[w].x -= mean; v[w].y -= mean; v[w].z -= mean; v[w].w -= mean;
        var += v[w].x*v[w].x + v[w].y*v[w].y + v[w].z*v[w].z + v[w].w*v[w].w;
    }
    #pragma unroll
    for (int o = 16; o > 0; o >>= 1) var += __shfl_xor_sync(~0u, var, o);
    float inv = rsqrtf(var * (1.0f / Dd) + EPSf);
    #pragma unroll
    for (int w = 0; w < 4; w++) {
        int idx = w*128 + lane*4;
        float4 gg = *(const float4*)&g[idx];
        float4 bb = *(const float4*)&b[idx];
        float y0 = v[w].x*inv*gg.x + bb.x, y1 = v[w].y*inv*gg.y + bb.y;
        float y2 = v[w].z*inv*gg.z + bb.z, y3 = v[w].w*inv*gg.w + bb.w;
        if (of) {
            float4 o4 = {y0, y1, y2, y3};
            *(float4*)&of[(size_t)row*Dd + idx] = o4;
        } else {
            __nv_bfloat16 h0 = __float2bfloat16_rn(y0), h1 = __float2bfloat16_rn(y1);
            __nv_bfloat16 h2 = __float2bfloat16_rn(y2), h3 = __float2bfloat16_rn(y3);
            __nv_bfloat162 hp0(h0, h1), hp1(h2, h3);
            __nv_bfloat162 lp0(__float2bfloat16_rn(y0 - bf2f(h0)), __float2bfloat16_rn(y1 - bf2f(h1)));
            __nv_bfloat162 lp1(__float2bfloat16_rn(y2 - bf2f(h2)), __float2bfloat16_rn(y3 - bf2f(h3)));
            uint2 uh = { *(uint32_t*)&hp0, *(uint32_t*)&hp1 };
            uint2 ul = { *(uint32_t*)&lp0, *(uint32_t*)&lp1 };
            *(uint2*)&ohi[(size_t)row*Dd + idx] = uh;
            *(uint2*)&olo[(size_t)row*Dd + idx] = ul;
        }
    }
}

// ---------------- fused attention: mma scores + FFMA PV ------------------------
// 16 q-rows/block, 256 threads, grid (32, H, B). qkv in bf16 hi/lo.
// smem layout (bytes):
//   0      kunion: khi[128][72]bf16 @0, klo @18432  (phase3: vs f32 [128][65])
//   36864  sc [16][520] f32
//   70144  qhi [16][72] bf16 | 72448 qlo
//   74752  qrs [16][16] f32 | 75776 pbin | 76800 rv[10][64] | 79360 rk[10][64]
#define SCS 520
#define ASMEM_TOTAL 81920
__global__ __launch_bounds__(256, 2) void attn_kernel(const float* __restrict__ relk,
                                                      const float* __restrict__ relv) {
    extern __shared__ char smx[];
    __nv_bfloat16* khi = (__nv_bfloat16*)smx;
    __nv_bfloat16* klo = (__nv_bfloat16*)(smx + 18432);
    float* vs   = (float*)smx;                 // phase3 alias
    float* sc   = (float*)(smx + 36864);
    __nv_bfloat16* qhi = (__nv_bfloat16*)(smx + 70144);
    __nv_bfloat16* qlo = (__nv_bfloat16*)(smx + 72448);
    float* qrs  = (float*)(smx + 74752);
    float* pbin = (float*)(smx + 75776);
    float* rv   = (float*)(smx + 76800);
    float* rk   = (float*)(smx + 79360);

    const int tid = threadIdx.x, w = tid >> 5, lane = tid & 31;
    const int n0 = blockIdx.x*16, h = blockIdx.y, b = blockIdx.z;
    const size_t tokbase = (size_t)(b*Nn);

    // load Q tile (hi/lo): 2 tensors x 16 rows x 8 16B-groups = 256 loads
    {
        int tensor = tid >> 7, idx = tid & 127, r = idx >> 3, cg = idx & 7;
        const __nv_bfloat16* src = (tensor ? g_qkvlo : g_qkvhi)
            + (tokbase + n0 + r)*1536 + h*DHd + cg*8;
        __nv_bfloat16* dst = (tensor ? qlo : qhi) + r*72 + cg*8;
        *(uint4*)dst = *(const uint4*)src;
    }
    for (int i = tid; i < Kb*DHd; i += 256) { rv[i] = relv[i]; rk[i] = relk[i]; }
    pbin[tid] = 0.f;
    __syncthreads();

    // qrel in-block from hi+lo
    if (tid < 16*Kb) {
        int qi = tid / Kb, j = tid % Kb;
        float dot = 0.f;
        #pragma unroll
        for (int d = 0; d < DHd; d++)
            dot += (bf2f(qhi[qi*72 + d]) + bf2f(qlo[qi*72 + d])) * rk[j*64 + d];
        qrs[qi*16 + j] = dot;
    }

    // fragment offsets (identical math to the verified GEMM kernel)
    const int which = lane >> 3, rowin = lane & 7;
    const uint32_t aoff = (((which & 1)*8 + rowin)*72 + (which >> 1)*8)*2;
    const uint32_t boff = ((w*16 + (which >> 1)*8 + rowin)*72 + (which & 1)*8)*2;
    const uint32_t uQhi = smem_to_u32(qhi), uQlo = smem_to_u32(qlo);
    const uint32_t uKhi = smem_to_u32(khi), uKlo = smem_to_u32(klo);
    const int g = lane >> 2, t2 = (lane & 3)*2;
    __syncthreads();

    // ---- phase 1: scores via 3-term bf16 mma ----
    for (int mc = 0; mc < 4; mc++) {
        for (int i = tid; i < 2048; i += 256) {
            int tensor = i >> 10, idx = i & 1023, r = idx >> 3, cg = idx & 7;
            const __nv_bfloat16* src = (tensor ? g_qkvlo : g_qkvhi)
                + (tokbase + mc*128 + r)*1536 + Dd + h*DHd + cg*8;
            __nv_bfloat16* dst = (tensor ? klo : khi) + r*72 + cg*8;
            *(uint4*)dst = *(const uint4*)src;
        }
        __syncthreads();
        float acc[2][4] = {};
        #pragma unroll
        for (int ks = 0; ks < 4; ks++) {
            uint32_t qh4[4], ql4[4], kh4[4], kl4[4];
            ldm_x4(qh4, uQhi + aoff + ks*32);
            ldm_x4(ql4, uQlo + aoff + ks*32);
            ldm_x4(kh4, uKhi + boff + ks*32);
            ldm_x4(kl4, uKlo + boff + ks*32);
            #pragma unroll
            for (int j = 0; j < 2; j++) {
                mma16816(acc[j], qh4, &kh4[j*2]);
                mma16816(acc[j], qh4, &kl4[j*2]);
                mma16816(acc[j], ql4, &kh4[j*2]);
            }
        }
        // epilogue: bias from qrs via idx, scale, store to sc
        #pragma unroll
        for (int j = 0; j < 2; j++) {
            int m = mc*128 + w*16 + j*8 + t2;
            const int* ir0 = g_idx + (tokbase + n0 + g)*Nn + m;
            const int* ir1 = g_idx + (tokbase + n0 + g + 8)*Nn + m;
            sc[g*SCS + m]       = (acc[j][0] + qrs[g*16 + ir0[0]]) * 0.125f;
            sc[g*SCS + m + 1]   = (acc[j][1] + qrs[g*16 + ir0[1]]) * 0.125f;
            sc[(g+8)*SCS + m]   = (acc[j][2] + qrs[(g+8)*16 + ir1[0]]) * 0.125f;
            sc[(g+8)*SCS + m+1] = (acc[j][3] + qrs[(g+8)*16 + ir1[1]]) * 0.125f;
        }
        __syncthreads();
    }

    // ---- phase 2: softmax (warp per 2 rows) + register bin mass ----
    #pragma unroll
    for (int rr = 0; rr < 2; rr++) {
        int row = w*2 + rr;
        float mx = -1e30f;
        for (int m = lane; m < 512; m += 32) mx = fmaxf(mx, sc[row*SCS + m]);
        #pragma unroll
        for (int o = 16; o > 0; o >>= 1) mx = fmaxf(mx, __shfl_xor_sync(~0u, mx, o));
        float sum = 0.f;
        for (int m = lane; m < 512; m += 32) {
            float e = expf(sc[row*SCS + m] - mx);
            sc[row*SCS + m] = e; sum += e;
        }
        #pragma unroll
        for (int o = 16; o > 0; o >>= 1) sum += __shfl_xor_sync(~0u, sum, o);
        float inv = 1.f / sum;
        float pb[Kb];
        #pragma unroll
        for (int j = 0; j < Kb; j++) pb[j] = 0.f;
        const int* ir = g_idx + (tokbase + n0 + row)*Nn;
        for (int m = lane; m < 512; m += 32) {
            float p = sc[row*SCS + m] * inv;
            sc[row*SCS + m] = p;
            int ji = ir[m];
            #pragma unroll
            for (int j = 0; j < Kb; j++) if (ji == j) pb[j] += p;
        }
        #pragma unroll
        for (int j = 0; j < Kb; j++) {
            float v = pb[j];
            #pragma unroll
            for (int o = 16; o > 0; o >>= 1) v += __shfl_xor_sync(~0u, v, o);
            if (lane == 0) pbin[row*16 + j] = v;
        }
    }
    __syncthreads();

    // ---- phase 3: attn @ v (V reconstructed hi+lo) ----
    const int d = tid & 63, s = tid >> 6;
    float acc[4] = {0,0,0,0};
    for (int mc = 0; mc < 4; mc++) {
        for (int i = tid; i < 2048; i += 256) {
            int r = i >> 4, c4 = (i & 15) << 2;
            size_t gaddr = (tokbase + mc*128 + r)*1536 + 2*Dd + h*DHd + c4;
            uint2 uh = *(const uint2*)&g_qkvhi[gaddr];
            uint2 ul = *(const uint2*)&g_qkvlo[gaddr];
            float2 h0 = __bfloat1622float2(*(__nv_bfloat162*)&uh.x);
            float2 h1 = __bfloat1622float2(*(__nv_bfloat162*)&uh.y);
            float2 l0 = __bfloat1622float2(*(__nv_bfloat162*)&ul.x);
            float2 l1 = __bfloat1622float2(*(__nv_bfloat162*)&ul.y);
            float* p = &vs[r*65 + c4];
            p[0] = h0.x + l0.x; p[1] = h0.y + l0.y;
            p[2] = h1.x + l1.x; p[3] = h1.y + l1.y;
        }
        __syncthreads();
        #pragma unroll 4
        for (int m4 = 0; m4 < 128; m4 += 4) {
            float v0 = vs[(m4+0)*65 + d], v1 = vs[(m4+1)*65 + d];
            float v2 = vs[(m4+2)*65 + d], v3 = vs[(m4+3)*65 + d];
            #pragma unroll
            for (int qq = 0; qq < 4; qq++) {
                float4 p = *(float4*)&sc[(s*4 + qq)*SCS + mc*128 + m4];
                acc[qq] += p.x*v0 + p.y*v1 + p.z*v2 + p.w*v3;
            }
        }
        __syncthreads();
    }
    #pragma unroll
    for (int qq = 0; qq < 4; qq++) {
        int qi = s*4 + qq;
        float o = acc[qq];
        #pragma unroll
        for (int j = 0; j < Kb; j++) o += pbin[qi*16 + j] * rv[j*64 + d];
        size_t tok = tokbase + n0 + qi;
        __nv_bfloat16 hb = __float2bfloat16_rn(o);
        g_ohi[tok*Dd + h*DHd + d] = hb;
        g_olo[tok*Dd + h*DHd + d] = __float2bfloat16_rn(o - bf2f(hb));
    }
}

// ---------------- bf16x3 mma GEMM, 3-stage cp.async + ldmatrix ----------------
// CTA 64(M)x128(N), BK=32, 256 thr, 8 warps 2x4 (warp 32x32).
#define SSTR 40
#define GSMEM_TOTAL 92160
__global__ __launch_bounds__(256, 2) void gemm_mma_kernel(
    const __nv_bfloat16* __restrict__ Ahi, const __nv_bfloat16* __restrict__ Alo,
    const __nv_bfloat16* __restrict__ Bhi, const __nv_bfloat16* __restrict__ Blo,
    const float* __restrict__ bias, const float* __restrict__ res,
    float* __restrict__ Cf, __nv_bfloat16* __restrict__ Chi, __nv_bfloat16* __restrict__ Clo,
    int Nc, int Kc, int doGelu) {
    extern __shared__ char smx[];
    __nv_bfloat16* sAhi = (__nv_bfloat16*)smx;            // [3][64*SSTR]
    __nv_bfloat16* sAlo = sAhi + 3*64*SSTR;
    __nv_bfloat16* sBhi = sAlo + 3*64*SSTR;               // [3][128*SSTR]
    __nv_bfloat16* sBlo = sBhi + 3*128*SSTR;

    const int tid = threadIdx.x, wid = tid >> 5, lane = tid & 31;
    const int g = lane >> 2, t2 = (lane & 3)*2;
    const int wm = (wid >> 2)*32, wn = (wid & 3)*32;
    const int m0 = blockIdx.y*64, n0 = blockIdx.x*128;

    const int ar = tid >> 2, ac = (tid & 3)*8;
    const int br0 = tid >> 2, bc0 = (tid & 3)*8;
    const int br1 = (tid + 256) >> 2, bc1 = ((tid + 256) & 3)*8;

    const int which = lane >> 3, rowin = lane & 7;
    uint32_t aoff[2], boff[2];
    #pragma unroll
    for (int i = 0; i < 2; i++)
        aoff[i] = ((wm + i*16 + (which & 1)*8 + rowin)*SSTR + (which >> 1)*8)*2;
    #pragma unroll
    for (int p = 0; p < 2; p++)
        boff[p] = ((wn + p*16 + (which >> 1)*8 + rowin)*SSTR + (which & 1)*8)*2;
    const uint32_t uAhi = smem_to_u32(sAhi), uAlo = smem_to_u32(sAlo);
    const uint32_t uBhi = smem_to_u32(sBhi), uBlo = smem_to_u32(sBlo);

    auto issue = [&](int c, int buf) {
        int kc = c*32;
        cpa16(&sAhi[buf*(64*SSTR) + ar*SSTR + ac], Ahi + (size_t)(m0 + ar)*Kc + kc + ac);
        cpa16(&sAlo[buf*(64*SSTR) + ar*SSTR + ac], Alo + (size_t)(m0 + ar)*Kc + kc + ac);
        cpa16(&sBhi[buf*(128*SSTR) + br0*SSTR + bc0], Bhi + (size_t)(n0 + br0)*Kc + kc + bc0);
        cpa16(&sBhi[buf*(128*SSTR) + br1*SSTR + bc1], Bhi + (size_t)(n0 + br1)*Kc + kc + bc1);
        cpa16(&sBlo[buf*(128*SSTR) + br0*SSTR + bc0], Blo + (size_t)(n0 + br0)*Kc + kc + bc0);
        cpa16(&sBlo[buf*(128*SSTR) + br1*SSTR + bc1], Blo + (size_t)(n0 + br1)*Kc + kc + bc1);
    };

    float acc[2][4][4] = {};
    const int nch = Kc >> 5;
    issue(0, 0); CP_COMMIT();
    issue(1, 1); CP_COMMIT();

    for (int c = 0; c < nch; c++) {
        int buf = c % 3;
        if (c + 2 < nch) {
            CP_WAIT(1);
            __syncthreads();
            issue(c + 2, (c + 2) % 3);
            CP_COMMIT();
        } else {
            CP_WAIT(0);
            __syncthreads();
        }
        const uint32_t offA = buf*(64*SSTR*2), offB = buf*(128*SSTR*2);
        #pragma unroll
        for (int ks = 0; ks < 32; ks += 16) {
            uint32_t ah[2][4], al[2][4], bh[8], bl[8];
            #pragma unroll
            for (int i = 0; i < 2; i++) {
                ldm_x4(ah[i], uAhi + offA + aoff[i] + ks*2);
                ldm_x4(al[i], uAlo + offA + aoff[i] + ks*2);
            }
            #pragma unroll
            for (int p = 0; p < 2; p++) {
                ldm_x4(&bh[p*4], uBhi + offB + boff[p] + ks*2);
                ldm_x4(&bl[p*4], uBlo + offB + boff[p] + ks*2);
            }
            #pragma unroll
            for (int i = 0; i < 2; i++)
                #pragma unroll
                for (int j = 0; j < 4; j++) {
                    mma16816(acc[i][j], ah[i], &bh[j*2]);
                    mma16816(acc[i][j], ah[i], &bl[j*2]);
                    mma16816(acc[i][j], al[i], &bh[j*2]);
                }
        }
    }

    // ---- epilogue ----
    #pragma unroll
    for (int i = 0; i < 2; i++) {
        int r0 = m0 + wm + i*16 + g;
        #pragma unroll
        for (int j = 0; j < 4; j++) {
            int col = n0 + wn + j*8 + t2;
            float b0 = bias[col], b1 = bias[col + 1];
            float2 v0 = { acc[i][j][0] + b0, acc[i][j][1] + b1 };
            float2 v1 = { acc[i][j][2] + b0, acc[i][j][3] + b1 };
            if (res) {
                float2 r0v = *(const float2*)&res[(size_t)r0*Nc + col];
                float2 r1v = *(const float2*)&res[(size_t)(r0 + 8)*Nc + col];
                v0.x += r0v.x; v0.y += r0v.y; v1.x += r1v.x; v1.y += r1v.y;
            }
            if (doGelu) {
                v0.x = 0.5f*v0.x*(1.f + erff(v0.x*0.70710678118654752f));
                v0.y = 0.5f*v0.y*(1.f + erff(v0.y*0.70710678118654752f));
                v1.x = 0.5f*v1.x*(1.f + erff(v1.x*0.70710678118654752f));
                v1.y = 0.5f*v1.y*(1.f + erff(v1.y*0.70710678118654752f));
            }
            if (Chi) {
                __nv_bfloat16 h00 = __float2bfloat16_rn(v0.x), h01 = __float2bfloat16_rn(v0.y);
                __nv_bfloat16 h10 = __float2bfloat16_rn(v1.x), h11 = __float2bfloat16_rn(v1.y);
                __nv_bfloat162 hp0(h00, h01), hp1(h10, h11);
                __nv_bfloat162 lp0(__float2bfloat16_rn(v0.x - bf2f(h00)), __float2bfloat16_rn(v0.y - bf2f(h01)));
                __nv_bfloat162 lp1(__float2bfloat16_rn(v1.x - bf2f(h10)), __float2bfloat16_rn(v1.y - bf2f(h11)));
                *(uint32_t*)&Chi[(size_t)r0*Nc + col]       = *(uint32_t*)&hp0;
                *(uint32_t*)&Chi[(size_t)(r0 + 8)*Nc + col] = *(uint32_t*)&hp1;
                *(uint32_t*)&Clo[(size_t)r0*Nc + col]       = *(uint32_t*)&lp0;
                *(uint32_t*)&Clo[(size_t)(r0 + 8)*Nc + col] = *(uint32_t*)&lp1;
            }
            if (Cf) {
                *(float2*)&Cf[(size_t)r0*Nc + col]       = v0;
                *(float2*)&Cf[(size_t)(r0 + 8)*Nc + col] = v1;
            }
        }
    }
}

// ---------------------------------------------------------------------------
extern "C" void kernel_launch(void* const* d_in, const int* in_sizes, int n_in,
                              void* d_out, int out_size) {
    const float* x     = (const float*)d_in[0];
    const float* coord = (const float*)d_in[1];
    const float* ln1_g = (const float*)d_in[2];
    const float* ln1_b = (const float*)d_in[3];
    const float* wq    = (const float*)d_in[4];
    const float* bq    = (const float*)d_in[5];
    const float* wk    = (const float*)d_in[6];
    const float* bk    = (const float*)d_in[7];
    const float* wv    = (const float*)d_in[8];
    const float* bv    = (const float*)d_in[9];
    const float* wo    = (const float*)d_in[10];
    const float* bo    = (const float*)d_in[11];
    const float* rel_k = (const float*)d_in[12];
    const float* rel_v = (const float*)d_in[13];
    const float* ln2_g = (const float*)d_in[14];
    const float* ln2_b = (const float*)d_in[15];
    const float* w1    = (const float*)d_in[16];
    const float* b1    = (const float*)d_in[17];
    const float* w2    = (const float*)d_in[18];
    const float* b2    = (const float*)d_in[19];
    const float* lnf_g = (const float*)d_in[20];
    const float* lnf_b = (const float*)d_in[21];

    float *px, *pbqkv;
    __nv_bfloat16 *pqkvhi, *pqkvlo, *phhi, *phlo, *pohi, *polo, *pfhi, *pflo, *pwhi, *pwlo;
    cudaGetSymbolAddress((void**)&px,     g_x);
    cudaGetSymbolAddress((void**)&pbqkv,  g_bqkv);
    cudaGetSymbolAddress((void**)&pqkvhi, g_qkvhi);
    cudaGetSymbolAddress((void**)&pqkvlo, g_qkvlo);
    cudaGetSymbolAddress((void**)&phhi,   g_hhi);
    cudaGetSymbolAddress((void**)&phlo,   g_hlo);
    cudaGetSymbolAddress((void**)&pohi,   g_ohi);
    cudaGetSymbolAddress((void**)&polo,   g_olo);
    cudaGetSymbolAddress((void**)&pfhi,   g_fhi);
    cudaGetSymbolAddress((void**)&pflo,   g_flo);
    cudaGetSymbolAddress((void**)&pwhi,   g_whi);
    cudaGetSymbolAddress((void**)&pwlo,   g_wlo);

    cudaFuncSetAttribute(gemm_mma_kernel, cudaFuncAttributeMaxDynamicSharedMemorySize, GSMEM_TOTAL);
    cudaFuncSetAttribute(attn_kernel, cudaFuncAttributeMaxDynamicSharedMemorySize, ASMEM_TOTAL);

    cudaMemcpyAsync(px, x, sizeof(float)*TOK*Dd, cudaMemcpyDeviceToDevice);
    idx_kernel<<<dim3(Nn, Bb), Nn>>>(coord);
    biaspack_kernel<<<(Ll*1536 + 255)/256, 256>>>(bq, bk, bv);
    wconv_all_kernel<<<dim3(16, 16, Ll*6), dim3(32, 8)>>>(wq, wk, wv, wo, w1, w2);

    const dim3 gQKV(12, 32);   // N=1536
    const dim3 gPRJ(4, 32);    // N=512
    const dim3 gFF1(16, 32);   // N=2048

    for (int l = 0; l < Ll; l++) {
        size_t lo = (size_t)l * WL_STRIDE;
        ln_kernel<<<TOK/8, 256>>>(px, ln1_g + l*Dd, ln1_b + l*Dd, phhi, phlo, nullptr);
        gemm_mma_kernel<<<gQKV, 256, GSMEM_TOTAL>>>(
            phhi, phlo, pwhi + lo, pwlo + lo, pbqkv + l*1536, nullptr,
            nullptr, pqkvhi, pqkvlo, 1536, 512, 0);
        attn_kernel<<<dim3(Nn/16, Hh, Bb), 256, ASMEM_TOTAL>>>(
            rel_k + (size_t)l*Kb*DHd, rel_v + (size_t)l*Kb*DHd);
        gemm_mma_kernel<<<gPRJ, 256, GSMEM_TOTAL>>>(
            pohi, polo, pwhi + lo + 786432, pwlo + lo + 786432, bo + l*Dd, px,
            px, nullptr, nullptr, 512, 512, 0);
        ln_kernel<<<TOK/8, 256>>>(px, ln2_g + l*Dd, ln2_b + l*Dd, phhi, phlo, nullptr);
        gemm_mma_kernel<<<gFF1, 256, GSMEM_TOTAL>>>(
            phhi, phlo, pwhi + lo + 1048576, pwlo + lo + 1048576, b1 + l*Mf, nullptr,
            nullptr, pfhi, pflo, 2048, 512, 1);
        gemm_mma_kernel<<<gPRJ, 256, GSMEM_TOTAL>>>(
            pfhi, pflo, pwhi + lo + 2097152, pwlo + lo + 2097152, b2 + l*Dd, px,
            px, nullptr, nullptr, 512, 2048, 0);
    }
    ln_kernel<<<TOK/8, 256>>>(px, lnf_g, lnf_b, nullptr, nullptr, (float*)d_out);
}

// round 9
// speedup vs baseline: 3.3366x; 1.1149x over previous
#include <cuda_runtime.h>
#include <cuda_bf16.h>
#include <cstdint>
#include <math.h>

// Problem constants
#define Bb   4
#define Nn   512
#define Dd   512
#define Hh   8
#define DHd  64
#define Kb   10
#define Mf   2048
#define Ll   4
#define TOK  (Bb*Nn)      // 2048
#define EPSf 1e-5f

// ---------------- scratch (device globals) ----------------------------------
__device__ float g_x[TOK*Dd];
__device__ unsigned char g_idx[Bb*Nn*Nn];
__device__ __nv_bfloat16 g_qkvhi[TOK*1536], g_qkvlo[TOK*1536];
__device__ __nv_bfloat16 g_hhi[TOK*Dd], g_hlo[TOK*Dd];
__device__ __nv_bfloat16 g_ohi[TOK*Dd], g_olo[TOK*Dd];
__device__ __nv_bfloat16 g_fhi[TOK*Mf], g_flo[TOK*Mf];
#define WL_STRIDE 3145728
__device__ __nv_bfloat16 g_whi[Ll*WL_STRIDE], g_wlo[Ll*WL_STRIDE];
__device__ float g_bqkv[Ll*1536];

// ---------------- helpers ----------------------------------------------------
__device__ __forceinline__ uint32_t smem_to_u32(const void* p) {
    uint32_t a;
    asm("{ .reg .u64 t; cvta.to.shared.u64 t, %1; cvt.u32.u64 %0, t; }"
        : "=r"(a) : "l"(p));
    return a;
}
__device__ __forceinline__ void cpa16(void* dst, const void* src) {
    uint32_t d = smem_to_u32(dst);
    asm volatile("cp.async.cg.shared.global [%0], [%1], 16;" :: "r"(d), "l"(src));
}
#define CP_COMMIT() asm volatile("cp.async.commit_group;" ::: "memory")
#define CP_WAIT(n)  asm volatile("cp.async.wait_group %0;" :: "n"(n) : "memory")

__device__ __forceinline__ void mma16816(float* c, const uint32_t* a, const uint32_t* b) {
    asm volatile("mma.sync.aligned.m16n8k16.row.col.f32.bf16.bf16.f32 "
        "{%0,%1,%2,%3}, {%4,%5,%6,%7}, {%8,%9}, {%0,%1,%2,%3};"
        : "+f"(c[0]), "+f"(c[1]), "+f"(c[2]), "+f"(c[3])
        : "r"(a[0]), "r"(a[1]), "r"(a[2]), "r"(a[3]), "r"(b[0]), "r"(b[1]));
}
__device__ __forceinline__ void ldm_x4(uint32_t* r, uint32_t addr) {
    asm volatile("ldmatrix.sync.aligned.m8n8.x4.shared.b16 {%0,%1,%2,%3}, [%4];"
        : "=r"(r[0]), "=r"(r[1]), "=r"(r[2]), "=r"(r[3]) : "r"(addr));
}
__device__ __forceinline__ void ldm_x4t(uint32_t* r, uint32_t addr) {
    asm volatile("ldmatrix.sync.aligned.m8n8.x4.trans.shared.b16 {%0,%1,%2,%3}, [%4];"
        : "=r"(r[0]), "=r"(r[1]), "=r"(r[2]), "=r"(r[3]) : "r"(addr));
}
__device__ __forceinline__ float bf2f(__nv_bfloat16 h) { return __bfloat162float(h); }

// ---------------- distance bins (uint8) ----------------------------------------
__global__ void idx_kernel(const float* __restrict__ coord) {
    int n = blockIdx.x, b = blockIdx.y, m = threadIdx.x;
    float2 cn = ((const float2*)coord)[b*Nn + n];
    float2 cm = ((const float2*)coord)[b*Nn + m];
    float dx = cn.x - cm.x, dy = cn.y - cm.y;
    float dist = sqrtf(dx*dx + dy*dy);
    int j = (int)floorf(dist);
    j = j < 0 ? 0 : (j > Kb-1 ? Kb-1 : j);
    g_idx[((size_t)(b*Nn + n))*Nn + m] = (unsigned char)j;
}

// ---------------- ALL weight transposes+splits in ONE launch -------------------
__global__ void wconv_all_kernel(const float* __restrict__ wq, const float* __restrict__ wk,
                                 const float* __restrict__ wv, const float* __restrict__ wo,
                                 const float* __restrict__ w1, const float* __restrict__ w2) {
    __shared__ float t[32][33];
    int z = blockIdx.z, l = z / 6, job = z % 6;
    const float* W; int K, N; size_t off;
    switch (job) {
        case 0: W = wq + (size_t)l*Dd*Dd; K = 512;  N = 512;  off = 0;       break;
        case 1: W = wk + (size_t)l*Dd*Dd; K = 512;  N = 512;  off = 262144;  break;
        case 2: W = wv + (size_t)l*Dd*Dd; K = 512;  N = 512;  off = 524288;  break;
        case 3: W = wo + (size_t)l*Dd*Dd; K = 512;  N = 512;  off = 786432;  break;
        case 4: W = w1 + (size_t)l*Dd*Mf; K = 512;  N = 2048; off = 1048576; break;
        default:W = w2 + (size_t)l*Mf*Dd; K = 2048; N = 512;  off = 2097152; break;
    }
    __nv_bfloat16* dh = g_whi + (size_t)l*WL_STRIDE + off;
    __nv_bfloat16* dl = g_wlo + (size_t)l*WL_STRIDE + off;
    int reps = (job >= 4) ? 4 : 1;
    int tx = threadIdx.x, ty = threadIdx.y;
    for (int r = 0; r < reps; r++) {
        int nn0, k0;
        if (job == 4)      { nn0 = (blockIdx.x + 16*r)*32; k0 = blockIdx.y*32; }
        else if (job == 5) { nn0 = blockIdx.x*32; k0 = (blockIdx.y + 16*r)*32; }
        else               { nn0 = blockIdx.x*32; k0 = blockIdx.y*32; }
        #pragma unroll
        for (int i = 0; i < 4; i++)
            t[ty + i*8][tx] = W[(size_t)(k0 + ty + i*8)*N + nn0 + tx];
        __syncthreads();
        #pragma unroll
        for (int i = 0; i < 4; i++) {
            int nl = ty + i*8;
            float v = t[tx][nl];
            __nv_bfloat16 hb = __float2bfloat16_rn(v);
            size_t o = (size_t)(nn0 + nl)*K + k0 + tx;
            dh[o] = hb; dl[o] = __float2bfloat16_rn(v - bf2f(hb));
        }
        __syncthreads();
    }
}

__global__ void biaspack_kernel(const float* __restrict__ bq,
                                const float* __restrict__ bk,
                                const float* __restrict__ bv) {
    int i = blockIdx.x*256 + threadIdx.x;
    if (i >= Ll*1536) return;
    int l = i / 1536, c = i % 1536;
    g_bqkv[i] = (c < 512) ? bq[l*512 + c]
              : (c < 1024 ? bk[l*512 + c - 512] : bv[l*512 + c - 1024]);
}

// ---------------- layernorm: warp per row, 8 rows/block ------------------------
__global__ __launch_bounds__(256) void ln_kernel(
    const float* __restrict__ x, const float* __restrict__ g, const float* __restrict__ b,
    __nv_bfloat16* __restrict__ ohi, __nv_bfloat16* __restrict__ olo,
    float* __restrict__ of) {
    int wid = threadIdx.x >> 5, lane = threadIdx.x & 31;
    int row = blockIdx.x*8 + wid;
    const float* xr = x + (size_t)row*Dd;
    float4 v[4];
    float sum = 0.f;
    #pragma unroll
    for (int w = 0; w < 4; w++) {
        v[w] = *(const float4*)&xr[w*128 + lane*4];
        sum += v[w].x + v[w].y + v[w].z + v[w].w;
    }
    #pragma unroll
    for (int o = 16; o > 0; o >>= 1) sum += __shfl_xor_sync(~0u, sum, o);
    float mean = sum * (1.0f / Dd);
    float var = 0.f;
    #pragma unroll
    for (int w = 0; w < 4; w++) {
        v[w].x -= mean; v[w].y -= mean; v[w].z -= mean; v[w].w -= mean;
        var += v[w].x*v[w].x + v[w].y*v[w].y + v[w].z*v[w].z + v[w].w*v[w].w;
    }
    #pragma unroll
    for (int o = 16; o > 0; o >>= 1) var += __shfl_xor_sync(~0u, var, o);
    float inv = rsqrtf(var * (1.0f / Dd) + EPSf);
    #pragma unroll
    for (int w = 0; w < 4; w++) {
        int idx = w*128 + lane*4;
        float4 gg = *(const float4*)&g[idx];
        float4 bb = *(const float4*)&b[idx];
        float y0 = v[w].x*inv*gg.x + bb.x, y1 = v[w].y*inv*gg.y + bb.y;
        float y2 = v[w].z*inv*gg.z + bb.z, y3 = v[w].w*inv*gg.w + bb.w;
        if (of) {
            float4 o4 = {y0, y1, y2, y3};
            *(float4*)&of[(size_t)row*Dd + idx] = o4;
        } else {
            __nv_bfloat16 h0 = __float2bfloat16_rn(y0), h1 = __float2bfloat16_rn(y1);
            __nv_bfloat16 h2 = __float2bfloat16_rn(y2), h3 = __float2bfloat16_rn(y3);
            __nv_bfloat162 hp0(h0, h1), hp1(h2, h3);
            __nv_bfloat162 lp0(__float2bfloat16_rn(y0 - bf2f(h0)), __float2bfloat16_rn(y1 - bf2f(h1)));
            __nv_bfloat162 lp1(__float2bfloat16_rn(y2 - bf2f(h2)), __float2bfloat16_rn(y3 - bf2f(h3)));
            uint2 uh = { *(uint32_t*)&hp0, *(uint32_t*)&hp1 };
            uint2 ul = { *(uint32_t*)&lp0, *(uint32_t*)&lp1 };
            *(uint2*)&ohi[(size_t)row*Dd + idx] = uh;
            *(uint2*)&olo[(size_t)row*Dd + idx] = ul;
        }
    }
}

// ---------------- fused attention: all-MMA scores + PV -------------------------
// 16 q-rows/block, 256 threads, grid (32, H, B).
// smem (bytes):
//   0       khi/vhi [128][72] bf16 (18432) | 18432 klo/vlo (18432)
//   36864   sc  [16][520] f32 (33280)   (phase3: out staging [2][16][68] f32)
//   70144   phh [16][520] bf16 (16640) | 86784 pll (16640)
//   103424  qhi [16][72] bf16 (2304)   | 105728 qlo (2304)
//   108032  qrs [16][16] f32 (1024)    | 109056 pbin [16][16] f32 (1024)
#define SCS 520
#define ASMEM_TOTAL 110080
__global__ __launch_bounds__(256, 2) void attn_kernel(const float* __restrict__ relk,
                                                      const float* __restrict__ relv) {
    extern __shared__ char smx[];
    __nv_bfloat16* khi = (__nv_bfloat16*)smx;
    __nv_bfloat16* klo = (__nv_bfloat16*)(smx + 18432);
    float* sc   = (float*)(smx + 36864);
    __nv_bfloat16* phh = (__nv_bfloat16*)(smx + 70144);
    __nv_bfloat16* pll = (__nv_bfloat16*)(smx + 86784);
    __nv_bfloat16* qhi = (__nv_bfloat16*)(smx + 103424);
    __nv_bfloat16* qlo = (__nv_bfloat16*)(smx + 105728);
    float* qrs  = (float*)(smx + 108032);
    float* pbin = (float*)(smx + 109056);

    const int tid = threadIdx.x, w = tid >> 5, lane = tid & 31;
    const int n0 = blockIdx.x*16, h = blockIdx.y, b = blockIdx.z;
    const size_t tokbase = (size_t)(b*Nn);

    // load Q tile (hi/lo)
    {
        int tensor = tid >> 7, idx = tid & 127, r = idx >> 3, cg = idx & 7;
        const __nv_bfloat16* src = (tensor ? g_qkvlo : g_qkvhi)
            + (tokbase + n0 + r)*1536 + h*DHd + cg*8;
        __nv_bfloat16* dst = (tensor ? qlo : qhi) + r*72 + cg*8;
        *(uint4*)dst = *(const uint4*)src;
    }
    pbin[tid] = 0.f;
    __syncthreads();

    // qrel in-block (relk straight from global; tiny + cached)
    if (tid < 16*Kb) {
        int qi = tid / Kb, j = tid % Kb;
        float dot = 0.f;
        #pragma unroll
        for (int d = 0; d < DHd; d++)
            dot += (bf2f(qhi[qi*72 + d]) + bf2f(qlo[qi*72 + d])) * relk[j*64 + d];
        qrs[qi*16 + j] = dot;
    }

    // fragment offsets
    const int which = lane >> 3, rowin = lane & 7;
    const uint32_t aoff = (((which & 1)*8 + rowin)*72 + (which >> 1)*8)*2;   // Q frags
    const uint32_t boff = ((w*16 + (which >> 1)*8 + rowin)*72 + (which & 1)*8)*2; // K frags
    const uint32_t uQhi = smem_to_u32(qhi), uQlo = smem_to_u32(qlo);
    const uint32_t uKhi = smem_to_u32(khi), uKlo = smem_to_u32(klo);
    const int g = lane >> 2, t2 = (lane & 3)*2;
    __syncthreads();

    // ---- phase 1: scores via 3-term bf16 mma ----
    for (int mc = 0; mc < 4; mc++) {
        for (int i = tid; i < 2048; i += 256) {
            int tensor = i >> 10, idx = i & 1023, r = idx >> 3, cg = idx & 7;
            const __nv_bfloat16* src = (tensor ? g_qkvlo : g_qkvhi)
                + (tokbase + mc*128 + r)*1536 + Dd + h*DHd + cg*8;
            __nv_bfloat16* dst = (tensor ? klo : khi) + r*72 + cg*8;
            *(uint4*)dst = *(const uint4*)src;
        }
        __syncthreads();
        float acc[2][4] = {};
        #pragma unroll
        for (int ks = 0; ks < 4; ks++) {
            uint32_t qh4[4], ql4[4], kh4[4], kl4[4];
            ldm_x4(qh4, uQhi + aoff + ks*32);
            ldm_x4(ql4, uQlo + aoff + ks*32);
            ldm_x4(kh4, uKhi + boff + ks*32);
            ldm_x4(kl4, uKlo + boff + ks*32);
            #pragma unroll
            for (int j = 0; j < 2; j++) {
                mma16816(acc[j], qh4, &kh4[j*2]);
                mma16816(acc[j], qh4, &kl4[j*2]);
                mma16816(acc[j], ql4, &kh4[j*2]);
            }
        }
        #pragma unroll
        for (int j = 0; j < 2; j++) {
            int m = mc*128 + w*16 + j*8 + t2;
            const unsigned char* ir0 = g_idx + (tokbase + n0 + g)*Nn + m;
            const unsigned char* ir1 = g_idx + (tokbase + n0 + g + 8)*Nn + m;
            sc[g*SCS + m]       = (acc[j][0] + qrs[g*16 + ir0[0]]) * 0.125f;
            sc[g*SCS + m + 1]   = (acc[j][1] + qrs[g*16 + ir0[1]]) * 0.125f;
            sc[(g+8)*SCS + m]   = (acc[j][2] + qrs[(g+8)*16 + ir1[0]]) * 0.125f;
            sc[(g+8)*SCS + m+1] = (acc[j][3] + qrs[(g+8)*16 + ir1[1]]) * 0.125f;
        }
        __syncthreads();
    }

    // ---- phase 2: softmax (warp per 2 rows); emit bf16 hi/lo probs + bins ----
    #pragma unroll
    for (int rr = 0; rr < 2; rr++) {
        int row = w*2 + rr;
        float mx = -1e30f;
        for (int m = lane; m < 512; m += 32) mx = fmaxf(mx, sc[row*SCS + m]);
        #pragma unroll
        for (int o = 16; o > 0; o >>= 1) mx = fmaxf(mx, __shfl_xor_sync(~0u, mx, o));
        float sum = 0.f;
        for (int m = lane; m < 512; m += 32) {
            float e = expf(sc[row*SCS + m] - mx);
            sc[row*SCS + m] = e; sum += e;
        }
        #pragma unroll
        for (int o = 16; o > 0; o >>= 1) sum += __shfl_xor_sync(~0u, sum, o);
        float inv = 1.f / sum;
        float pb[Kb];
        #pragma unroll
        for (int j = 0; j < Kb; j++) pb[j] = 0.f;
        const unsigned char* ir = g_idx + (tokbase + n0 + row)*Nn;
        for (int m = lane; m < 512; m += 32) {
            float p = sc[row*SCS + m] * inv;
            __nv_bfloat16 ph = __float2bfloat16_rn(p);
            phh[row*SCS + m] = ph;
            pll[row*SCS + m] = __float2bfloat16_rn(p - bf2f(ph));
            int ji = ir[m];
            #pragma unroll
            for (int j = 0; j < Kb; j++) if (ji == j) pb[j] += p;
        }
        #pragma unroll
        for (int j = 0; j < Kb; j++) {
            float v = pb[j];
            #pragma unroll
            for (int o = 16; o > 0; o >>= 1) v += __shfl_xor_sync(~0u, v, o);
            if (lane == 0) pbin[row*16 + j] = v;
        }
    }
    __syncthreads();

    // ---- phase 3: P @ V via 3-term mma (warps: 4 n16-cols x 2 k-halves) ----
    const int n0w = (w & 3)*16, khalf = w >> 2;
    const uint32_t uPh = smem_to_u32(phh), uPl = smem_to_u32(pll);
    const uint32_t paoff = (((which & 1)*8 + rowin)*SCS + (which >> 1)*8)*2;
    const uint32_t pboff = (((which & 1)*8 + rowin)*72 + n0w + (which >> 1)*8)*2;
    float c0[4] = {}, c1[4] = {};
    for (int mc = 0; mc < 4; mc++) {
        for (int i = tid; i < 2048; i += 256) {
            int tensor = i >> 10, idx = i & 1023, r = idx >> 3, cg = idx & 7;
            const __nv_bfloat16* src = (tensor ? g_qkvlo : g_qkvhi)
                + (tokbase + mc*128 + r)*1536 + 2*Dd + h*DHd + cg*8;
            __nv_bfloat16* dst = (tensor ? klo : khi) + r*72 + cg*8;
            *(uint4*)dst = *(const uint4*)src;
        }
        __syncthreads();
        #pragma unroll
        for (int ks = 0; ks < 4; ks++) {
            int kP = mc*128 + khalf*64 + ks*16;   // col in P
            int kV = khalf*64 + ks*16;            // row in V chunk
            uint32_t ph4[4], pl4[4], vh4[4], vl4[4];
            ldm_x4(ph4, uPh + paoff + kP*2);
            ldm_x4(pl4, uPl + paoff + kP*2);
            ldm_x4t(vh4, uKhi + pboff + kV*144);
            ldm_x4t(vl4, uKlo + pboff + kV*144);
            mma16816(c0, ph4, &vh4[0]);
            mma16816(c0, ph4, &vl4[0]);
            mma16816(c0, pl4, &vh4[0]);
            mma16816(c1, ph4, &vh4[2]);
            mma16816(c1, ph4, &vl4[2]);
            mma16816(c1, pl4, &vh4[2]);
        }
        __syncthreads();
    }
    // stage partials (reuse sc region): out[khalf][16][68]
    {
        float* outp = sc + khalf*(16*68);
        outp[g*68 + n0w + t2]          = c0[0];
        outp[g*68 + n0w + t2 + 1]      = c0[1];
        outp[(g+8)*68 + n0w + t2]      = c0[2];
        outp[(g+8)*68 + n0w + t2 + 1]  = c0[3];
        outp[g*68 + n0w + 8 + t2]      = c1[0];
        outp[g*68 + n0w + 8 + t2 + 1]  = c1[1];
        outp[(g+8)*68 + n0w + 8 + t2]  = c1[2];
        outp[(g+8)*68 + n0w + 8 + t2+1]= c1[3];
    }
    __syncthreads();
    for (int i = tid; i < 1024; i += 256) {
        int qi = i >> 6, d = i & 63;
        float o = sc[qi*68 + d] + sc[16*68 + qi*68 + d];
        #pragma unroll
        for (int j = 0; j < Kb; j++) o += pbin[qi*16 + j] * relv[j*64 + d];
        size_t tok = tokbase + n0 + qi;
        __nv_bfloat16 hb = __float2bfloat16_rn(o);
        g_ohi[tok*Dd + h*DHd + d] = hb;
        g_olo[tok*Dd + h*DHd + d] = __float2bfloat16_rn(o - bf2f(hb));
    }
}

// ---------------- bf16x3 mma GEMM, 3-stage cp.async + ldmatrix ----------------
#define SSTR 40
#define GSMEM_TOTAL 92160
__global__ __launch_bounds__(256, 2) void gemm_mma_kernel(
    const __nv_bfloat16* __restrict__ Ahi, const __nv_bfloat16* __restrict__ Alo,
    const __nv_bfloat16* __restrict__ Bhi, const __nv_bfloat16* __restrict__ Blo,
    const float* __restrict__ bias, const float* __restrict__ res,
    float* __restrict__ Cf, __nv_bfloat16* __restrict__ Chi, __nv_bfloat16* __restrict__ Clo,
    int Nc, int Kc, int doGelu) {
    extern __shared__ char smx[];
    __nv_bfloat16* sAhi = (__nv_bfloat16*)smx;
    __nv_bfloat16* sAlo = sAhi + 3*64*SSTR;
    __nv_bfloat16* sBhi = sAlo + 3*64*SSTR;
    __nv_bfloat16* sBlo = sBhi + 3*128*SSTR;

    const int tid = threadIdx.x, wid = tid >> 5, lane = tid & 31;
    const int g = lane >> 2, t2 = (lane & 3)*2;
    const int wm = (wid >> 2)*32, wn = (wid & 3)*32;
    const int m0 = blockIdx.y*64, n0 = blockIdx.x*128;

    const int ar = tid >> 2, ac = (tid & 3)*8;
    const int br0 = tid >> 2, bc0 = (tid & 3)*8;
    const int br1 = (tid + 256) >> 2, bc1 = ((tid + 256) & 3)*8;

    const int which = lane >> 3, rowin = lane & 7;
    uint32_t aoff[2], boff[2];
    #pragma unroll
    for (int i = 0; i < 2; i++)
        aoff[i] = ((wm + i*16 + (which & 1)*8 + rowin)*SSTR + (which >> 1)*8)*2;
    #pragma unroll
    for (int p = 0; p < 2; p++)
        boff[p] = ((wn + p*16 + (which >> 1)*8 + rowin)*SSTR + (which & 1)*8)*2;
    const uint32_t uAhi = smem_to_u32(sAhi), uAlo = smem_to_u32(sAlo);
    const uint32_t uBhi = smem_to_u32(sBhi), uBlo = smem_to_u32(sBlo);

    auto issue = [&](int c, int buf) {
        int kc = c*32;
        cpa16(&sAhi[buf*(64*SSTR) + ar*SSTR + ac], Ahi + (size_t)(m0 + ar)*Kc + kc + ac);
        cpa16(&sAlo[buf*(64*SSTR) + ar*SSTR + ac], Alo + (size_t)(m0 + ar)*Kc + kc + ac);
        cpa16(&sBhi[buf*(128*SSTR) + br0*SSTR + bc0], Bhi + (size_t)(n0 + br0)*Kc + kc + bc0);
        cpa16(&sBhi[buf*(128*SSTR) + br1*SSTR + bc1], Bhi + (size_t)(n0 + br1)*Kc + kc + bc1);
        cpa16(&sBlo[buf*(128*SSTR) + br0*SSTR + bc0], Blo + (size_t)(n0 + br0)*Kc + kc + bc0);
        cpa16(&sBlo[buf*(128*SSTR) + br1*SSTR + bc1], Blo + (size_t)(n0 + br1)*Kc + kc + bc1);
    };

    float acc[2][4][4] = {};
    const int nch = Kc >> 5;
    issue(0, 0); CP_COMMIT();
    issue(1, 1); CP_COMMIT();

    for (int c = 0; c < nch; c++) {
        int buf = c % 3;
        if (c + 2 < nch) {
            CP_WAIT(1);
            __syncthreads();
            issue(c + 2, (c + 2) % 3);
            CP_COMMIT();
        } else {
            CP_WAIT(0);
            __syncthreads();
        }
        const uint32_t offA = buf*(64*SSTR*2), offB = buf*(128*SSTR*2);
        #pragma unroll
        for (int ks = 0; ks < 32; ks += 16) {
            uint32_t ah[2][4], al[2][4], bh[8], bl[8];
            #pragma unroll
            for (int i = 0; i < 2; i++) {
                ldm_x4(ah[i], uAhi + offA + aoff[i] + ks*2);
                ldm_x4(al[i], uAlo + offA + aoff[i] + ks*2);
            }
            #pragma unroll
            for (int p = 0; p < 2; p++) {
                ldm_x4(&bh[p*4], uBhi + offB + boff[p] + ks*2);
                ldm_x4(&bl[p*4], uBlo + offB + boff[p] + ks*2);
            }
            #pragma unroll
            for (int i = 0; i < 2; i++)
                #pragma unroll
                for (int j = 0; j < 4; j++) {
                    mma16816(acc[i][j], ah[i], &bh[j*2]);
                    mma16816(acc[i][j], ah[i], &bl[j*2]);
                    mma16816(acc[i][j], al[i], &bh[j*2]);
                }
        }
    }

    #pragma unroll
    for (int i = 0; i < 2; i++) {
        int r0 = m0 + wm + i*16 + g;
        #pragma unroll
        for (int j = 0; j < 4; j++) {
            int col = n0 + wn + j*8 + t2;
            float b0 = bias[col], b1 = bias[col + 1];
            float2 v0 = { acc[i][j][0] + b0, acc[i][j][1] + b1 };
            float2 v1 = { acc[i][j][2] + b0, acc[i][j][3] + b1 };
            if (res) {
                float2 r0v = *(const float2*)&res[(size_t)r0*Nc + col];
                float2 r1v = *(const float2*)&res[(size_t)(r0 + 8)*Nc + col];
                v0.x += r0v.x; v0.y += r0v.y; v1.x += r1v.x; v1.y += r1v.y;
            }
            if (doGelu) {
                v0.x = 0.5f*v0.x*(1.f + erff(v0.x*0.70710678118654752f));
                v0.y = 0.5f*v0.y*(1.f + erff(v0.y*0.70710678118654752f));
                v1.x = 0.5f*v1.x*(1.f + erff(v1.x*0.70710678118654752f));
                v1.y = 0.5f*v1.y*(1.f + erff(v1.y*0.70710678118654752f));
            }
            if (Chi) {
                __nv_bfloat16 h00 = __float2bfloat16_rn(v0.x), h01 = __float2bfloat16_rn(v0.y);
                __nv_bfloat16 h10 = __float2bfloat16_rn(v1.x), h11 = __float2bfloat16_rn(v1.y);
                __nv_bfloat162 hp0(h00, h01), hp1(h10, h11);
                __nv_bfloat162 lp0(__float2bfloat16_rn(v0.x - bf2f(h00)), __float2bfloat16_rn(v0.y - bf2f(h01)));
                __nv_bfloat162 lp1(__float2bfloat16_rn(v1.x - bf2f(h10)), __float2bfloat16_rn(v1.y - bf2f(h11)));
                *(uint32_t*)&Chi[(size_t)r0*Nc + col]       = *(uint32_t*)&hp0;
                *(uint32_t*)&Chi[(size_t)(r0 + 8)*Nc + col] = *(uint32_t*)&hp1;
                *(uint32_t*)&Clo[(size_t)r0*Nc + col]       = *(uint32_t*)&lp0;
                *(uint32_t*)&Clo[(size_t)(r0 + 8)*Nc + col] = *(uint32_t*)&lp1;
            }
            if (Cf) {
                *(float2*)&Cf[(size_t)r0*Nc + col]       = v0;
                *(float2*)&Cf[(size_t)(r0 + 8)*Nc + col] = v1;
            }
        }
    }
}

// ---------------------------------------------------------------------------
extern "C" void kernel_launch(void* const* d_in, const int* in_sizes, int n_in,
                              void* d_out, int out_size) {
    const float* x     = (const float*)d_in[0];
    const float* coord = (const float*)d_in[1];
    const float* ln1_g = (const float*)d_in[2];
    const float* ln1_b = (const float*)d_in[3];
    const float* wq    = (const float*)d_in[4];
    const float* bq    = (const float*)d_in[5];
    const float* wk    = (const float*)d_in[6];
    const float* bk    = (const float*)d_in[7];
    const float* wv    = (const float*)d_in[8];
    const float* bv    = (const float*)d_in[9];
    const float* wo    = (const float*)d_in[10];
    const float* bo    = (const float*)d_in[11];
    const float* rel_k = (const float*)d_in[12];
    const float* rel_v = (const float*)d_in[13];
    const float* ln2_g = (const float*)d_in[14];
    const float* ln2_b = (const float*)d_in[15];
    const float* w1    = (const float*)d_in[16];
    const float* b1    = (const float*)d_in[17];
    const float* w2    = (const float*)d_in[18];
    const float* b2    = (const float*)d_in[19];
    const float* lnf_g = (const float*)d_in[20];
    const float* lnf_b = (const float*)d_in[21];

    float *px;
    __nv_bfloat16 *pqkvhi, *pqkvlo, *phhi, *phlo, *pohi, *polo, *pfhi, *pflo, *pwhi, *pwlo;
    float *pbqkv;
    cudaGetSymbolAddress((void**)&px,     g_x);
    cudaGetSymbolAddress((void**)&pbqkv,  g_bqkv);
    cudaGetSymbolAddress((void**)&pqkvhi, g_qkvhi);
    cudaGetSymbolAddress((void**)&pqkvlo, g_qkvlo);
    cudaGetSymbolAddress((void**)&phhi,   g_hhi);
    cudaGetSymbolAddress((void**)&phlo,   g_hlo);
    cudaGetSymbolAddress((void**)&pohi,   g_ohi);
    cudaGetSymbolAddress((void**)&polo,   g_olo);
    cudaGetSymbolAddress((void**)&pfhi,   g_fhi);
    cudaGetSymbolAddress((void**)&pflo,   g_flo);
    cudaGetSymbolAddress((void**)&pwhi,   g_whi);
    cudaGetSymbolAddress((void**)&pwlo,   g_wlo);

    cudaFuncSetAttribute(gemm_mma_kernel, cudaFuncAttributeMaxDynamicSharedMemorySize, GSMEM_TOTAL);
    cudaFuncSetAttribute(attn_kernel, cudaFuncAttributeMaxDynamicSharedMemorySize, ASMEM_TOTAL);

    // setup (ordered so ncu -s 5 lands on attn / qkv-gemm)
    wconv_all_kernel<<<dim3(16, 16, Ll*6), dim3(32, 8)>>>(wq, wk, wv, wo, w1, w2);
    biaspack_kernel<<<(Ll*1536 + 255)/256, 256>>>(bq, bk, bv);
    idx_kernel<<<dim3(Nn, Bb), Nn>>>(coord);
    cudaMemcpyAsync(px, x, sizeof(float)*TOK*Dd, cudaMemcpyDeviceToDevice);

    const dim3 gQKV(12, 32);   // N=1536
    const dim3 gPRJ(4, 32);    // N=512
    const dim3 gFF1(16, 32);   // N=2048

    for (int l = 0; l < Ll; l++) {
        size_t lo = (size_t)l * WL_STRIDE;
        ln_kernel<<<TOK/8, 256>>>(px, ln1_g + l*Dd, ln1_b + l*Dd, phhi, phlo, nullptr);
        gemm_mma_kernel<<<gQKV, 256, GSMEM_TOTAL>>>(
            phhi, phlo, pwhi + lo, pwlo + lo, pbqkv + l*1536, nullptr,
            nullptr, pqkvhi, pqkvlo, 1536, 512, 0);
        attn_kernel<<<dim3(Nn/16, Hh, Bb), 256, ASMEM_TOTAL>>>(
            rel_k + (size_t)l*Kb*DHd, rel_v + (size_t)l*Kb*DHd);
        gemm_mma_kernel<<<gPRJ, 256, GSMEM_TOTAL>>>(
            pohi, polo, pwhi + lo + 786432, pwlo + lo + 786432, bo + l*Dd, px,
            px, nullptr, nullptr, 512, 512, 0);
        ln_kernel<<<TOK/8, 256>>>(px, ln2_g + l*Dd, ln2_b + l*Dd, phhi, phlo, nullptr);
        gemm_mma_kernel<<<gFF1, 256, GSMEM_TOTAL>>>(
            phhi, phlo, pwhi + lo + 1048576, pwlo + lo + 1048576, b1 + l*Mf, nullptr,
            nullptr, pfhi, pflo, 2048, 512, 1);
        gemm_mma_kernel<<<gPRJ, 256, GSMEM_TOTAL>>>(
            pfhi, pflo, pwhi + lo + 2097152, pwlo + lo + 2097152, b2 + l*Dd, px,
            px, nullptr, nullptr, 512, 2048, 0);
    }
    ln_kernel<<<TOK/8, 256>>>(px, lnf_g, lnf_b, nullptr, nullptr, (float*)d_out);
}

// round 10
// speedup vs baseline: 3.3432x; 1.0020x over previous
#include <cuda_runtime.h>
#include <cuda_bf16.h>
#include <cstdint>
#include <math.h>

// Problem constants
#define Bb   4
#define Nn   512
#define Dd   512
#define Hh   8
#define DHd  64
#define Kb   10
#define Mf   2048
#define Ll   4
#define TOK  (Bb*Nn)      // 2048
#define EPSf 1e-5f

// ---------------- scratch (device globals) ----------------------------------
__device__ float g_x[TOK*Dd];
__device__ unsigned char g_idx[Bb*Nn*Nn];
__device__ __nv_bfloat16 g_qkvhi[TOK*1536], g_qkvlo[TOK*1536];
__device__ __nv_bfloat16 g_hhi[TOK*Dd], g_hlo[TOK*Dd];
__device__ __nv_bfloat16 g_ohi[TOK*Dd], g_olo[TOK*Dd];
__device__ __nv_bfloat16 g_fhi[TOK*Mf], g_flo[TOK*Mf];
#define WL_STRIDE 3145728
__device__ __nv_bfloat16 g_whi[Ll*WL_STRIDE], g_wlo[Ll*WL_STRIDE];
__device__ float g_bqkv[Ll*1536];

// ---------------- helpers ----------------------------------------------------
__device__ __forceinline__ uint32_t smem_to_u32(const void* p) {
    uint32_t a;
    asm("{ .reg .u64 t; cvta.to.shared.u64 t, %1; cvt.u32.u64 %0, t; }"
        : "=r"(a) : "l"(p));
    return a;
}
__device__ __forceinline__ void cpa16(void* dst, const void* src) {
    uint32_t d = smem_to_u32(dst);
    asm volatile("cp.async.cg.shared.global [%0], [%1], 16;" :: "r"(d), "l"(src));
}
#define CP_COMMIT() asm volatile("cp.async.commit_group;" ::: "memory")
#define CP_WAIT(n)  asm volatile("cp.async.wait_group %0;" :: "n"(n) : "memory")

__device__ __forceinline__ void mma16816(float* c, const uint32_t* a, const uint32_t* b) {
    asm volatile("mma.sync.aligned.m16n8k16.row.col.f32.bf16.bf16.f32 "
        "{%0,%1,%2,%3}, {%4,%5,%6,%7}, {%8,%9}, {%0,%1,%2,%3};"
        : "+f"(c[0]), "+f"(c[1]), "+f"(c[2]), "+f"(c[3])
        : "r"(a[0]), "r"(a[1]), "r"(a[2]), "r"(a[3]), "r"(b[0]), "r"(b[1]));
}
__device__ __forceinline__ void ldm_x4(uint32_t* r, uint32_t addr) {
    asm volatile("ldmatrix.sync.aligned.m8n8.x4.shared.b16 {%0,%1,%2,%3}, [%4];"
        : "=r"(r[0]), "=r"(r[1]), "=r"(r[2]), "=r"(r[3]) : "r"(addr));
}
__device__ __forceinline__ void ldm_x4t(uint32_t* r, uint32_t addr) {
    asm volatile("ldmatrix.sync.aligned.m8n8.x4.trans.shared.b16 {%0,%1,%2,%3}, [%4];"
        : "=r"(r[0]), "=r"(r[1]), "=r"(r[2]), "=r"(r[3]) : "r"(addr));
}
__device__ __forceinline__ float bf2f(__nv_bfloat16 h) { return __bfloat162float(h); }

// FMA-pipe exp: e^x = 2^(x*log2e); n=rint(t), deg-5 poly on f in [-0.5,0.5].
// rel err ~2e-6; valid for x <= 0 (softmax post-max-subtract), x >= -80.
__device__ __forceinline__ float fexp(float x) {
    float t = x * 1.4426950408889634f;
    float n = rintf(t);
    float f = t - n;
    float p = 1.3534581e-3f;
    p = fmaf(p, f, 9.6181291e-3f);
    p = fmaf(p, f, 5.5504109e-2f);
    p = fmaf(p, f, 2.4022651e-1f);
    p = fmaf(p, f, 6.9314718e-1f);
    p = fmaf(p, f, 1.0f);
    return p * __int_as_float(((int)n + 127) << 23);
}

// ---------------- distance bins (uint8) ----------------------------------------
__global__ void idx_kernel(const float* __restrict__ coord) {
    int n = blockIdx.x, b = blockIdx.y, m = threadIdx.x;
    float2 cn = ((const float2*)coord)[b*Nn + n];
    float2 cm = ((const float2*)coord)[b*Nn + m];
    float dx = cn.x - cm.x, dy = cn.y - cm.y;
    float dist = sqrtf(dx*dx + dy*dy);
    int j = (int)floorf(dist);
    j = j < 0 ? 0 : (j > Kb-1 ? Kb-1 : j);
    g_idx[((size_t)(b*Nn + n))*Nn + m] = (unsigned char)j;
}

// ---------------- ALL weight transposes+splits in ONE launch -------------------
__global__ void wconv_all_kernel(const float* __restrict__ wq, const float* __restrict__ wk,
                                 const float* __restrict__ wv, const float* __restrict__ wo,
                                 const float* __restrict__ w1, const float* __restrict__ w2) {
    __shared__ float t[32][33];
    int z = blockIdx.z, l = z / 6, job = z % 6;
    const float* W; int K, N; size_t off;
    switch (job) {
        case 0: W = wq + (size_t)l*Dd*Dd; K = 512;  N = 512;  off = 0;       break;
        case 1: W = wk + (size_t)l*Dd*Dd; K = 512;  N = 512;  off = 262144;  break;
        case 2: W = wv + (size_t)l*Dd*Dd; K = 512;  N = 512;  off = 524288;  break;
        case 3: W = wo + (size_t)l*Dd*Dd; K = 512;  N = 512;  off = 786432;  break;
        case 4: W = w1 + (size_t)l*Dd*Mf; K = 512;  N = 2048; off = 1048576; break;
        default:W = w2 + (size_t)l*Mf*Dd; K = 2048; N = 512;  off = 2097152; break;
    }
    __nv_bfloat16* dh = g_whi + (size_t)l*WL_STRIDE + off;
    __nv_bfloat16* dl = g_wlo + (size_t)l*WL_STRIDE + off;
    int reps = (job >= 4) ? 4 : 1;
    int tx = threadIdx.x, ty = threadIdx.y;
    for (int r = 0; r < reps; r++) {
        int nn0, k0;
        if (job == 4)      { nn0 = (blockIdx.x + 16*r)*32; k0 = blockIdx.y*32; }
        else if (job == 5) { nn0 = blockIdx.x*32; k0 = (blockIdx.y + 16*r)*32; }
        else               { nn0 = blockIdx.x*32; k0 = blockIdx.y*32; }
        #pragma unroll
        for (int i = 0; i < 4; i++)
            t[ty + i*8][tx] = W[(size_t)(k0 + ty + i*8)*N + nn0 + tx];
        __syncthreads();
        #pragma unroll
        for (int i = 0; i < 4; i++) {
            int nl = ty + i*8;
            float v = t[tx][nl];
            __nv_bfloat16 hb = __float2bfloat16_rn(v);
            size_t o = (size_t)(nn0 + nl)*K + k0 + tx;
            dh[o] = hb; dl[o] = __float2bfloat16_rn(v - bf2f(hb));
        }
        __syncthreads();
    }
}

__global__ void biaspack_kernel(const float* __restrict__ bq,
                                const float* __restrict__ bk,
                                const float* __restrict__ bv) {
    int i = blockIdx.x*256 + threadIdx.x;
    if (i >= Ll*1536) return;
    int l = i / 1536, c = i % 1536;
    g_bqkv[i] = (c < 512) ? bq[l*512 + c]
              : (c < 1024 ? bk[l*512 + c - 512] : bv[l*512 + c - 1024]);
}

// ---------------- layernorm: warp per row, 8 rows/block ------------------------
__global__ __launch_bounds__(256) void ln_kernel(
    const float* __restrict__ x, const float* __restrict__ g, const float* __restrict__ b,
    __nv_bfloat16* __restrict__ ohi, __nv_bfloat16* __restrict__ olo,
    float* __restrict__ of) {
    int wid = threadIdx.x >> 5, lane = threadIdx.x & 31;
    int row = blockIdx.x*8 + wid;
    const float* xr = x + (size_t)row*Dd;
    float4 v[4];
    float sum = 0.f;
    #pragma unroll
    for (int w = 0; w < 4; w++) {
        v[w] = *(const float4*)&xr[w*128 + lane*4];
        sum += v[w].x + v[w].y + v[w].z + v[w].w;
    }
    #pragma unroll
    for (int o = 16; o > 0; o >>= 1) sum += __shfl_xor_sync(~0u, sum, o);
    float mean = sum * (1.0f / Dd);
    float var = 0.f;
    #pragma unroll
    for (int w = 0; w < 4; w++) {
        v[w].x -= mean; v[w].y -= mean; v[w].z -= mean; v[w].w -= mean;
        var += v[w].x*v[w].x + v[w].y*v[w].y + v[w].z*v[w].z + v[w].w*v[w].w;
    }
    #pragma unroll
    for (int o = 16; o > 0; o >>= 1) var += __shfl_xor_sync(~0u, var, o);
    float inv = rsqrtf(var * (1.0f / Dd) + EPSf);
    #pragma unroll
    for (int w = 0; w < 4; w++) {
        int idx = w*128 + lane*4;
        float4 gg = *(const float4*)&g[idx];
        float4 bb = *(const float4*)&b[idx];
        float y0 = v[w].x*inv*gg.x + bb.x, y1 = v[w].y*inv*gg.y + bb.y;
        float y2 = v[w].z*inv*gg.z + bb.z, y3 = v[w].w*inv*gg.w + bb.w;
        if (of) {
            float4 o4 = {y0, y1, y2, y3};
            *(float4*)&of[(size_t)row*Dd + idx] = o4;
        } else {
            __nv_bfloat16 h0 = __float2bfloat16_rn(y0), h1 = __float2bfloat16_rn(y1);
            __nv_bfloat16 h2 = __float2bfloat16_rn(y2), h3 = __float2bfloat16_rn(y3);
            __nv_bfloat162 hp0(h0, h1), hp1(h2, h3);
            __nv_bfloat162 lp0(__float2bfloat16_rn(y0 - bf2f(h0)), __float2bfloat16_rn(y1 - bf2f(h1)));
            __nv_bfloat162 lp1(__float2bfloat16_rn(y2 - bf2f(h2)), __float2bfloat16_rn(y3 - bf2f(h3)));
            uint2 uh = { *(uint32_t*)&hp0, *(uint32_t*)&hp1 };
            uint2 ul = { *(uint32_t*)&lp0, *(uint32_t*)&lp1 };
            *(uint2*)&ohi[(size_t)row*Dd + idx] = uh;
            *(uint2*)&olo[(size_t)row*Dd + idx] = ul;
        }
    }
}

// ---------------- fused attention: all-MMA scores + PV -------------------------
// 16 q-rows/block, 256 threads, grid (32, H, B).
#define SCS 520
#define ASMEM_TOTAL 110080
__global__ __launch_bounds__(256, 2) void attn_kernel(const float* __restrict__ relk,
                                                      const float* __restrict__ relv) {
    extern __shared__ char smx[];
    __nv_bfloat16* khi = (__nv_bfloat16*)smx;
    __nv_bfloat16* klo = (__nv_bfloat16*)(smx + 18432);
    float* sc   = (float*)(smx + 36864);
    __nv_bfloat16* phh = (__nv_bfloat16*)(smx + 70144);
    __nv_bfloat16* pll = (__nv_bfloat16*)(smx + 86784);
    __nv_bfloat16* qhi = (__nv_bfloat16*)(smx + 103424);
    __nv_bfloat16* qlo = (__nv_bfloat16*)(smx + 105728);
    float* qrs  = (float*)(smx + 108032);
    float* pbin = (float*)(smx + 109056);

    const int tid = threadIdx.x, w = tid >> 5, lane = tid & 31;
    const int n0 = blockIdx.x*16, h = blockIdx.y, b = blockIdx.z;
    const size_t tokbase = (size_t)(b*Nn);

    // load Q tile (hi/lo)
    {
        int tensor = tid >> 7, idx = tid & 127, r = idx >> 3, cg = idx & 7;
        const __nv_bfloat16* src = (tensor ? g_qkvlo : g_qkvhi)
            + (tokbase + n0 + r)*1536 + h*DHd + cg*8;
        __nv_bfloat16* dst = (tensor ? qlo : qhi) + r*72 + cg*8;
        *(uint4*)dst = *(const uint4*)src;
    }
    pbin[tid] = 0.f;
    // prefetch K chunk 0 (async) — overlaps with qrel compute
    for (int i = tid; i < 2048; i += 256) {
        int tensor = i >> 10, idx = i & 1023, r = idx >> 3, cg = idx & 7;
        const __nv_bfloat16* src = (tensor ? g_qkvlo : g_qkvhi)
            + (tokbase + r)*1536 + Dd + h*DHd + cg*8;
        __nv_bfloat16* dst = (tensor ? klo : khi) + r*72 + cg*8;
        cpa16(dst, src);
    }
    CP_COMMIT();
    __syncthreads();

    // qrel in-block
    if (tid < 16*Kb) {
        int qi = tid / Kb, j = tid % Kb;
        float dot = 0.f;
        #pragma unroll
        for (int d = 0; d < DHd; d++)
            dot += (bf2f(qhi[qi*72 + d]) + bf2f(qlo[qi*72 + d])) * relk[j*64 + d];
        qrs[qi*16 + j] = dot;
    }

    const int which = lane >> 3, rowin = lane & 7;
    const uint32_t aoff = (((which & 1)*8 + rowin)*72 + (which >> 1)*8)*2;
    const uint32_t boff = ((w*16 + (which >> 1)*8 + rowin)*72 + (which & 1)*8)*2;
    const uint32_t uQhi = smem_to_u32(qhi), uQlo = smem_to_u32(qlo);
    const uint32_t uKhi = smem_to_u32(khi), uKlo = smem_to_u32(klo);
    const int g = lane >> 2, t2 = (lane & 3)*2;

    // ---- phase 1: scores via 3-term bf16 mma ----
    for (int mc = 0; mc < 4; mc++) {
        if (mc == 0) {
            CP_WAIT(0);
        } else {
            for (int i = tid; i < 2048; i += 256) {
                int tensor = i >> 10, idx = i & 1023, r = idx >> 3, cg = idx & 7;
                const __nv_bfloat16* src = (tensor ? g_qkvlo : g_qkvhi)
                    + (tokbase + mc*128 + r)*1536 + Dd + h*DHd + cg*8;
                __nv_bfloat16* dst = (tensor ? klo : khi) + r*72 + cg*8;
                *(uint4*)dst = *(const uint4*)src;
            }
        }
        __syncthreads();
        float acc[2][4] = {};
        #pragma unroll
        for (int ks = 0; ks < 4; ks++) {
            uint32_t qh4[4], ql4[4], kh4[4], kl4[4];
            ldm_x4(qh4, uQhi + aoff + ks*32);
            ldm_x4(ql4, uQlo + aoff + ks*32);
            ldm_x4(kh4, uKhi + boff + ks*32);
            ldm_x4(kl4, uKlo + boff + ks*32);
            #pragma unroll
            for (int j = 0; j < 2; j++) {
                mma16816(acc[j], qh4, &kh4[j*2]);
                mma16816(acc[j], qh4, &kl4[j*2]);
                mma16816(acc[j], ql4, &kh4[j*2]);
            }
        }
        #pragma unroll
        for (int j = 0; j < 2; j++) {
            int m = mc*128 + w*16 + j*8 + t2;
            const unsigned char* ir0 = g_idx + (tokbase + n0 + g)*Nn + m;
            const unsigned char* ir1 = g_idx + (tokbase + n0 + g + 8)*Nn + m;
            sc[g*SCS + m]       = (acc[j][0] + qrs[g*16 + ir0[0]]) * 0.125f;
            sc[g*SCS + m + 1]   = (acc[j][1] + qrs[g*16 + ir0[1]]) * 0.125f;
            sc[(g+8)*SCS + m]   = (acc[j][2] + qrs[(g+8)*16 + ir1[0]]) * 0.125f;
            sc[(g+8)*SCS + m+1] = (acc[j][3] + qrs[(g+8)*16 + ir1[1]]) * 0.125f;
        }
        __syncthreads();
    }

    // prefetch V chunk 0 (async) — overlaps with softmax
    for (int i = tid; i < 2048; i += 256) {
        int tensor = i >> 10, idx = i & 1023, r = idx >> 3, cg = idx & 7;
        const __nv_bfloat16* src = (tensor ? g_qkvlo : g_qkvhi)
            + (tokbase + r)*1536 + 2*Dd + h*DHd + cg*8;
        __nv_bfloat16* dst = (tensor ? klo : khi) + r*72 + cg*8;
        cpa16(dst, src);
    }
    CP_COMMIT();

    // ---- phase 2: softmax (warp per 2 rows); emit bf16 hi/lo probs + bins ----
    #pragma unroll
    for (int rr = 0; rr < 2; rr++) {
        int row = w*2 + rr;
        float mx = -1e30f;
        for (int m = lane; m < 512; m += 32) mx = fmaxf(mx, sc[row*SCS + m]);
        #pragma unroll
        for (int o = 16; o > 0; o >>= 1) mx = fmaxf(mx, __shfl_xor_sync(~0u, mx, o));
        float sum = 0.f;
        for (int m = lane; m < 512; m += 32) {
            float e = fexp(sc[row*SCS + m] - mx);
            sc[row*SCS + m] = e; sum += e;
        }
        #pragma unroll
        for (int o = 16; o > 0; o >>= 1) sum += __shfl_xor_sync(~0u, sum, o);
        float inv = 1.f / sum;
        float pb[Kb];
        #pragma unroll
        for (int j = 0; j < Kb; j++) pb[j] = 0.f;
        const unsigned char* ir = g_idx + (tokbase + n0 + row)*Nn;
        for (int m = lane; m < 512; m += 32) {
            float p = sc[row*SCS + m] * inv;
            __nv_bfloat16 ph = __float2bfloat16_rn(p);
            phh[row*SCS + m] = ph;
            pll[row*SCS + m] = __float2bfloat16_rn(p - bf2f(ph));
            int ji = ir[m];
            #pragma unroll
            for (int j = 0; j < Kb; j++) if (ji == j) pb[j] += p;
        }
        #pragma unroll
        for (int j = 0; j < Kb; j++) {
            float v = pb[j];
            #pragma unroll
            for (int o = 16; o > 0; o >>= 1) v += __shfl_xor_sync(~0u, v, o);
            if (lane == 0) pbin[row*16 + j] = v;
        }
    }

    // ---- phase 3: P @ V via 3-term mma (warps: 4 n16-cols x 2 k-halves) ----
    const int n0w = (w & 3)*16, khalf = w >> 2;
    const uint32_t uPh = smem_to_u32(phh), uPl = smem_to_u32(pll);
    const uint32_t paoff = (((which & 1)*8 + rowin)*SCS + (which >> 1)*8)*2;
    const uint32_t pboff = (((which & 1)*8 + rowin)*72 + n0w + (which >> 1)*8)*2;
    float c0[4] = {}, c1[4] = {};
    for (int mc = 0; mc < 4; mc++) {
        if (mc == 0) {
            CP_WAIT(0);
        } else {
            for (int i = tid; i < 2048; i += 256) {
                int tensor = i >> 10, idx = i & 1023, r = idx >> 3, cg = idx & 7;
                const __nv_bfloat16* src = (tensor ? g_qkvlo : g_qkvhi)
                    + (tokbase + mc*128 + r)*1536 + 2*Dd + h*DHd + cg*8;
                __nv_bfloat16* dst = (tensor ? klo : khi) + r*72 + cg*8;
                *(uint4*)dst = *(const uint4*)src;
            }
        }
        __syncthreads();
        #pragma unroll
        for (int ks = 0; ks < 4; ks++) {
            int kP = mc*128 + khalf*64 + ks*16;
            int kV = khalf*64 + ks*16;
            uint32_t ph4[4], pl4[4], vh4[4], vl4[4];
            ldm_x4(ph4, uPh + paoff + kP*2);
            ldm_x4(pl4, uPl + paoff + kP*2);
            ldm_x4t(vh4, uKhi + pboff + kV*144);
            ldm_x4t(vl4, uKlo + pboff + kV*144);
            mma16816(c0, ph4, &vh4[0]);
            mma16816(c0, ph4, &vl4[0]);
            mma16816(c0, pl4, &vh4[0]);
            mma16816(c1, ph4, &vh4[2]);
            mma16816(c1, ph4, &vl4[2]);
            mma16816(c1, pl4, &vh4[2]);
        }
        __syncthreads();
    }
    {
        float* outp = sc + khalf*(16*68);
        outp[g*68 + n0w + t2]          = c0[0];
        outp[g*68 + n0w + t2 + 1]      = c0[1];
        outp[(g+8)*68 + n0w + t2]      = c0[2];
        outp[(g+8)*68 + n0w + t2 + 1]  = c0[3];
        outp[g*68 + n0w + 8 + t2]      = c1[0];
        outp[g*68 + n0w + 8 + t2 + 1]  = c1[1];
        outp[(g+8)*68 + n0w + 8 + t2]  = c1[2];
        outp[(g+8)*68 + n0w + 8 + t2+1]= c1[3];
    }
    __syncthreads();
    for (int i = tid; i < 1024; i += 256) {
        int qi = i >> 6, d = i & 63;
        float o = sc[qi*68 + d] + sc[16*68 + qi*68 + d];
        #pragma unroll
        for (int j = 0; j < Kb; j++) o += pbin[qi*16 + j] * relv[j*64 + d];
        size_t tok = tokbase + n0 + qi;
        __nv_bfloat16 hb = __float2bfloat16_rn(o);
        g_ohi[tok*Dd + h*DHd + d] = hb;
        g_olo[tok*Dd + h*DHd + d] = __float2bfloat16_rn(o - bf2f(hb));
    }
}

// ---------------- bf16x3 mma GEMM, 3-stage cp.async + ldmatrix ----------------
#define SSTR 40
#define GSMEM_TOTAL 92160
__global__ __launch_bounds__(256, 2) void gemm_mma_kernel(
    const __nv_bfloat16* __restrict__ Ahi, const __nv_bfloat16* __restrict__ Alo,
    const __nv_bfloat16* __restrict__ Bhi, const __nv_bfloat16* __restrict__ Blo,
    const float* __restrict__ bias, const float* __restrict__ res,
    float* __restrict__ Cf, __nv_bfloat16* __restrict__ Chi, __nv_bfloat16* __restrict__ Clo,
    int Nc, int Kc, int doGelu) {
    extern __shared__ char smx[];
    __nv_bfloat16* sAhi = (__nv_bfloat16*)smx;
    __nv_bfloat16* sAlo = sAhi + 3*64*SSTR;
    __nv_bfloat16* sBhi = sAlo + 3*64*SSTR;
    __nv_bfloat16* sBlo = sBhi + 3*128*SSTR;

    const int tid = threadIdx.x, wid = tid >> 5, lane = tid & 31;
    const int g = lane >> 2, t2 = (lane & 3)*2;
    const int wm = (wid >> 2)*32, wn = (wid & 3)*32;
    const int m0 = blockIdx.y*64, n0 = blockIdx.x*128;

    const int ar = tid >> 2, ac = (tid & 3)*8;
    const int br0 = tid >> 2, bc0 = (tid & 3)*8;
    const int br1 = (tid + 256) >> 2, bc1 = ((tid + 256) & 3)*8;

    const int which = lane >> 3, rowin = lane & 7;
    uint32_t aoff[2], boff[2];
    #pragma unroll
    for (int i = 0; i < 2; i++)
        aoff[i] = ((wm + i*16 + (which & 1)*8 + rowin)*SSTR + (which >> 1)*8)*2;
    #pragma unroll
    for (int p = 0; p < 2; p++)
        boff[p] = ((wn + p*16 + (which >> 1)*8 + rowin)*SSTR + (which & 1)*8)*2;
    const uint32_t uAhi = smem_to_u32(sAhi), uAlo = smem_to_u32(sAlo);
    const uint32_t uBhi = smem_to_u32(sBhi), uBlo = smem_to_u32(sBlo);

    auto issue = [&](int c, int buf) {
        int kc = c*32;
        cpa16(&sAhi[buf*(64*SSTR) + ar*SSTR + ac], Ahi + (size_t)(m0 + ar)*Kc + kc + ac);
        cpa16(&sAlo[buf*(64*SSTR) + ar*SSTR + ac], Alo + (size_t)(m0 + ar)*Kc + kc + ac);
        cpa16(&sBhi[buf*(128*SSTR) + br0*SSTR + bc0], Bhi + (size_t)(n0 + br0)*Kc + kc + bc0);
        cpa16(&sBhi[buf*(128*SSTR) + br1*SSTR + bc1], Bhi + (size_t)(n0 + br1)*Kc + kc + bc1);
        cpa16(&sBlo[buf*(128*SSTR) + br0*SSTR + bc0], Blo + (size_t)(n0 + br0)*Kc + kc + bc0);
        cpa16(&sBlo[buf*(128*SSTR) + br1*SSTR + bc1], Blo + (size_t)(n0 + br1)*Kc + kc + bc1);
    };

    float acc[2][4][4] = {};
    const int nch = Kc >> 5;
    issue(0, 0); CP_COMMIT();
    issue(1, 1); CP_COMMIT();

    for (int c = 0; c < nch; c++) {
        int buf = c % 3;
        if (c + 2 < nch) {
            CP_WAIT(1);
            __syncthreads();
            issue(c + 2, (c + 2) % 3);
            CP_COMMIT();
        } else {
            CP_WAIT(0);
            __syncthreads();
        }
        const uint32_t offA = buf*(64*SSTR*2), offB = buf*(128*SSTR*2);
        #pragma unroll
        for (int ks = 0; ks < 32; ks += 16) {
            uint32_t ah[2][4], al[2][4], bh[8], bl[8];
            #pragma unroll
            for (int i = 0; i < 2; i++) {
                ldm_x4(ah[i], uAhi + offA + aoff[i] + ks*2);
                ldm_x4(al[i], uAlo + offA + aoff[i] + ks*2);
            }
            #pragma unroll
            for (int p = 0; p < 2; p++) {
                ldm_x4(&bh[p*4], uBhi + offB + boff[p] + ks*2);
                ldm_x4(&bl[p*4], uBlo + offB + boff[p] + ks*2);
            }
            #pragma unroll
            for (int i = 0; i < 2; i++)
                #pragma unroll
                for (int j = 0; j < 4; j++) {
                    mma16816(acc[i][j], ah[i], &bh[j*2]);
                    mma16816(acc[i][j], ah[i], &bl[j*2]);
                    mma16816(acc[i][j], al[i], &bh[j*2]);
                }
        }
    }

    #pragma unroll
    for (int i = 0; i < 2; i++) {
        int r0 = m0 + wm + i*16 + g;
        #pragma unroll
        for (int j = 0; j < 4; j++) {
            int col = n0 + wn + j*8 + t2;
            float b0 = bias[col], b1 = bias[col + 1];
            float2 v0 = { acc[i][j][0] + b0, acc[i][j][1] + b1 };
            float2 v1 = { acc[i][j][2] + b0, acc[i][j][3] + b1 };
            if (res) {
                float2 r0v = *(const float2*)&res[(size_t)r0*Nc + col];
                float2 r1v = *(const float2*)&res[(size_t)(r0 + 8)*Nc + col];
                v0.x += r0v.x; v0.y += r0v.y; v1.x += r1v.x; v1.y += r1v.y;
            }
            if (doGelu) {
                v0.x = 0.5f*v0.x*(1.f + erff(v0.x*0.70710678118654752f));
                v0.y = 0.5f*v0.y*(1.f + erff(v0.y*0.70710678118654752f));
                v1.x = 0.5f*v1.x*(1.f + erff(v1.x*0.70710678118654752f));
                v1.y = 0.5f*v1.y*(1.f + erff(v1.y*0.70710678118654752f));
            }
            if (Chi) {
                __nv_bfloat16 h00 = __float2bfloat16_rn(v0.x), h01 = __float2bfloat16_rn(v0.y);
                __nv_bfloat16 h10 = __float2bfloat16_rn(v1.x), h11 = __float2bfloat16_rn(v1.y);
                __nv_bfloat162 hp0(h00, h01), hp1(h10, h11);
                __nv_bfloat162 lp0(__float2bfloat16_rn(v0.x - bf2f(h00)), __float2bfloat16_rn(v0.y - bf2f(h01)));
                __nv_bfloat162 lp1(__float2bfloat16_rn(v1.x - bf2f(h10)), __float2bfloat16_rn(v1.y - bf2f(h11)));
                *(uint32_t*)&Chi[(size_t)r0*Nc + col]       = *(uint32_t*)&hp0;
                *(uint32_t*)&Chi[(size_t)(r0 + 8)*Nc + col] = *(uint32_t*)&hp1;
                *(uint32_t*)&Clo[(size_t)r0*Nc + col]       = *(uint32_t*)&lp0;
                *(uint32_t*)&Clo[(size_t)(r0 + 8)*Nc + col] = *(uint32_t*)&lp1;
            }
            if (Cf) {
                *(float2*)&Cf[(size_t)r0*Nc + col]       = v0;
                *(float2*)&Cf[(size_t)(r0 + 8)*Nc + col] = v1;
            }
        }
    }
}

// ---------------------------------------------------------------------------
extern "C" void kernel_launch(void* const* d_in, const int* in_sizes, int n_in,
                              void* d_out, int out_size) {
    const float* x     = (const float*)d_in[0];
    const float* coord = (const float*)d_in[1];
    const float* ln1_g = (const float*)d_in[2];
    const float* ln1_b = (const float*)d_in[3];
    const float* wq    = (const float*)d_in[4];
    const float* bq    = (const float*)d_in[5];
    const float* wk    = (const float*)d_in[6];
    const float* bk    = (const float*)d_in[7];
    const float* wv    = (const float*)d_in[8];
    const float* bv    = (const float*)d_in[9];
    const float* wo    = (const float*)d_in[10];
    const float* bo    = (const float*)d_in[11];
    const float* rel_k = (const float*)d_in[12];
    const float* rel_v = (const float*)d_in[13];
    const float* ln2_g = (const float*)d_in[14];
    const float* ln2_b = (const float*)d_in[15];
    const float* w1    = (const float*)d_in[16];
    const float* b1    = (const float*)d_in[17];
    const float* w2    = (const float*)d_in[18];
    const float* b2    = (const float*)d_in[19];
    const float* lnf_g = (const float*)d_in[20];
    const float* lnf_b = (const float*)d_in[21];

    float *px, *pbqkv;
    __nv_bfloat16 *pqkvhi, *pqkvlo, *phhi, *phlo, *pohi, *polo, *pfhi, *pflo, *pwhi, *pwlo;
    cudaGetSymbolAddress((void**)&px,     g_x);
    cudaGetSymbolAddress((void**)&pbqkv,  g_bqkv);
    cudaGetSymbolAddress((void**)&pqkvhi, g_qkvhi);
    cudaGetSymbolAddress((void**)&pqkvlo, g_qkvlo);
    cudaGetSymbolAddress((void**)&phhi,   g_hhi);
    cudaGetSymbolAddress((void**)&phlo,   g_hlo);
    cudaGetSymbolAddress((void**)&pohi,   g_ohi);
    cudaGetSymbolAddress((void**)&polo,   g_olo);
    cudaGetSymbolAddress((void**)&pfhi,   g_fhi);
    cudaGetSymbolAddress((void**)&pflo,   g_flo);
    cudaGetSymbolAddress((void**)&pwhi,   g_whi);
    cudaGetSymbolAddress((void**)&pwlo,   g_wlo);

    cudaFuncSetAttribute(gemm_mma_kernel, cudaFuncAttributeMaxDynamicSharedMemorySize, GSMEM_TOTAL);
    cudaFuncSetAttribute(attn_kernel, cudaFuncAttributeMaxDynamicSharedMemorySize, ASMEM_TOTAL);

    wconv_all_kernel<<<dim3(16, 16, Ll*6), dim3(32, 8)>>>(wq, wk, wv, wo, w1, w2);
    biaspack_kernel<<<(Ll*1536 + 255)/256, 256>>>(bq, bk, bv);
    idx_kernel<<<dim3(Nn, Bb), Nn>>>(coord);
    cudaMemcpyAsync(px, x, sizeof(float)*TOK*Dd, cudaMemcpyDeviceToDevice);

    const dim3 gQKV(12, 32);   // N=1536
    const dim3 gPRJ(4, 32);    // N=512
    const dim3 gFF1(16, 32);   // N=2048

    for (int l = 0; l < Ll; l++) {
        size_t lo = (size_t)l * WL_STRIDE;
        ln_kernel<<<TOK/8, 256>>>(px, ln1_g + l*Dd, ln1_b + l*Dd, phhi, phlo, nullptr);
        gemm_mma_kernel<<<gQKV, 256, GSMEM_TOTAL>>>(
            phhi, phlo, pwhi + lo, pwlo + lo, pbqkv + l*1536, nullptr,
            nullptr, pqkvhi, pqkvlo, 1536, 512, 0);
        attn_kernel<<<dim3(Nn/16, Hh, Bb), 256, ASMEM_TOTAL>>>(
            rel_k + (size_t)l*Kb*DHd, rel_v + (size_t)l*Kb*DHd);
        gemm_mma_kernel<<<gPRJ, 256, GSMEM_TOTAL>>>(
            pohi, polo, pwhi + lo + 786432, pwlo + lo + 786432, bo + l*Dd, px,
            px, nullptr, nullptr, 512, 512, 0);
        ln_kernel<<<TOK/8, 256>>>(px, ln2_g + l*Dd, ln2_b + l*Dd, phhi, phlo, nullptr);
        gemm_mma_kernel<<<gFF1, 256, GSMEM_TOTAL>>>(
            phhi, phlo, pwhi + lo + 1048576, pwlo + lo + 1048576, b1 + l*Mf, nullptr,
            nullptr, pfhi, pflo, 2048, 512, 1);
        gemm_mma_kernel<<<gPRJ, 256, GSMEM_TOTAL>>>(
            pfhi, pflo, pwhi + lo + 2097152, pwlo + lo + 2097152, b2 + l*Dd, px,
            px, nullptr, nullptr, 512, 2048, 0);
    }
    ln_kernel<<<TOK/8, 256>>>(px, lnf_g, lnf_b, nullptr, nullptr, (float*)d_out);
}